// round 12
// baseline (speedup 1.0000x reference)
#include <cuda_runtime.h>
#include <cuda_bf16.h>
#include <cstdint>
#include <math.h>

#define BSZ   64
#define NLEAF 256
#define ED    512
#define DD    512
#define UD    512

// ---------------------------------------------------------------------------
// scratch (device globals; no allocation allowed)
// ---------------------------------------------------------------------------
__device__ __nv_bfloat16 g_leafhi[BSZ * NLEAF * DD];
__device__ __nv_bfloat16 g_leaflo[BSZ * NLEAF * DD];
__device__ __nv_bfloat16 g_levhi [BSZ * 255  * DD];
__device__ __nv_bfloat16 g_levlo [BSZ * 255  * DD];
__device__ __nv_bfloat16 g_Wjhi[512 * 1024], g_Wjlo[512 * 1024];  // [n][k] bf16 (joins 2-8)
__device__ __nv_bfloat16 g_Bzhi[2048 * 1024], g_Bzlo[2048 * 1024];// [n][k] (kern;rec)
__device__ __nv_bfloat16 g_zAhi[BSZ * 1024],  g_zAlo[BSZ * 1024]; // [tree|h0]
// int8 quantized operands (2-digit, per-row scale)
__device__ int8_t g_qAh[BSZ * NLEAF * ED],  g_qAl[BSZ * NLEAF * ED];   // inputs
__device__ int8_t g_qLh[BSZ * NLEAF * DD],  g_qLl[BSZ * NLEAF * DD];   // leaf
__device__ int8_t g_qWth[512 * 512],  g_qWtl[512 * 512];
__device__ int8_t g_qWhh[512 * 512],  g_qWhl[512 * 512];
__device__ int8_t g_qWjh[512 * 1024], g_qWjl[512 * 1024];
__device__ float g_sA  [BSZ * NLEAF];
__device__ float g_sLP [BSZ * NLEAF / 2];     // leaf pair scales
__device__ float g_sWt [512], g_sWh[512], g_sWj[512];
__device__ float g_z4    [4 * BSZ * 2048];
__device__ float g_part  [128 * 128 * 64];
__device__ float g_mr    [BSZ * 255];
__device__ float g_attn  [BSZ * NLEAF];
__device__ float g_sctrl [BSZ];
__device__ float g_tctrl [BSZ];
__device__ float g_biasc [BSZ * DD];
__device__ float g_upd   [BSZ * NLEAF];
__device__ int      g_bar_count;
__device__ unsigned g_bar_gen;

__constant__ int c_roff[9] = {0, 0, 8192, 12288, 14336, 15360, 15872, 16128, 16256};
__constant__ int c_Mt[6] = {16, 8, 4, 2, 1, 1};
__constant__ int c_S [6] = {1,  2, 4, 8, 8, 8};
static const int h_roff[9] = {0, 0, 8192, 12288, 14336, 15360, 15872, 16128, 16256};

__device__ __forceinline__ float sigf(float x) { return 1.f / (1.f + __expf(-x)); }

__device__ __forceinline__ uint32_t smem_u32(const void* p) {
    uint32_t a;
    asm("{ .reg .u64 t; cvta.to.shared.u64 t, %1; cvt.u32.u64 %0, t; }" : "=r"(a) : "l"(p));
    return a;
}

__device__ __forceinline__ void cp_async16(uint32_t dst, const void* src) {
    asm volatile("cp.async.cg.shared.global [%0], [%1], 16;" :: "r"(dst), "l"(src));
}
__device__ __forceinline__ void cp_commit() {
    asm volatile("cp.async.commit_group;" ::: "memory");
}
template <int N>
__device__ __forceinline__ void cp_wait() {
    asm volatile("cp.async.wait_group %0;" :: "n"(N) : "memory");
}

__device__ __forceinline__ void ldsm_x4(uint32_t (&r)[4], uint32_t addr) {
    asm volatile("ldmatrix.sync.aligned.m8n8.x4.shared.b16 {%0,%1,%2,%3}, [%4];"
                 : "=r"(r[0]), "=r"(r[1]), "=r"(r[2]), "=r"(r[3]) : "r"(addr));
}

__device__ __forceinline__ void mma16816(float (&d)[4], const uint32_t (&a)[4],
                                         uint32_t b0, uint32_t b1) {
    asm volatile(
        "mma.sync.aligned.m16n8k16.row.col.f32.bf16.bf16.f32 "
        "{%0,%1,%2,%3},{%4,%5,%6,%7},{%8,%9},{%0,%1,%2,%3};"
        : "+f"(d[0]), "+f"(d[1]), "+f"(d[2]), "+f"(d[3])
        : "r"(a[0]), "r"(a[1]), "r"(a[2]), "r"(a[3]), "r"(b0), "r"(b1));
}

__device__ __forceinline__ void mma_s8(int (&d)[4], const uint32_t (&a)[4],
                                       uint32_t b0, uint32_t b1) {
    asm volatile(
        "mma.sync.aligned.m16n8k32.row.col.s32.s8.s8.s32 "
        "{%0,%1,%2,%3},{%4,%5,%6,%7},{%8,%9},{%0,%1,%2,%3};"
        : "+r"(d[0]), "+r"(d[1]), "+r"(d[2]), "+r"(d[3])
        : "r"(a[0]), "r"(a[1]), "r"(a[2]), "r"(a[3]), "r"(b0), "r"(b1));
}

// quantize x (scaled by inv = 16256/amax) into 2 base-128 digits
__device__ __forceinline__ void quant2(float x, float inv, int8_t& hi, int8_t& lo) {
    const float t = x * inv;
    const int h = __float2int_rn(t * 0.0078125f);
    const int l = __float2int_rn(t - 128.f * (float)h);
    hi = (int8_t)h; lo = (int8_t)l;
}

__device__ __forceinline__ float warp_max(float m) {
#pragma unroll
    for (int o = 16; o; o >>= 1) m = fmaxf(m, __shfl_xor_sync(0xffffffffu, m, o));
    return m;
}

#define ROWB 144
#define SMEM_128 (3 * (2 * 128 * ROWB + 2 * 128 * ROWB))
#define SMEM_64  (4 * (2 * 128 * ROWB + 2 * 64  * ROWB))

// ---------------------------------------------------------------------------
// bf16 GEMM tile body (unchanged; used for join2-8 and LSTM)
// ---------------------------------------------------------------------------
template <int EPI, int NT, int NS, int THREADS>
__device__ __forceinline__ void gemm_tile(
    const __nv_bfloat16* __restrict__ Ahi, const __nv_bfloat16* __restrict__ Alo,
    const __nv_bfloat16* __restrict__ Bhi, const __nv_bfloat16* __restrict__ Blo,
    float* __restrict__ C, __nv_bfloat16* Chi, __nv_bfloat16* Clo,
    int M, int K, int lda, int ldb, int ldc,
    int row0, int col0, uint32_t sbase)
{
    constexpr int PLANE_A = 128 * ROWB;
    constexpr int PLANE_B = NT * ROWB;
    constexpr int STAGE_B = 2 * PLANE_A + 2 * PLANE_B;
    constexpr int NWARPS  = THREADS / 32;
    constexpr int NWN     = NT / 32;
    constexpr int NWM     = NWARPS / NWN;
    constexpr int MF      = 128 / (16 * NWM);

    const int tid  = threadIdx.x;
    const int lane = tid & 31;
    const int wid  = tid >> 5;
    const int wm   = wid % NWM;
    const int wn   = wid / NWM;

    const __nv_bfloat16* srcs[4] = {Ahi, Alo, Bhi, Blo};

    const int laneRowA = (lane & 7) + ((lane >> 3) & 1) * 8;
    const int laneKA   = ((lane >> 4) & 1) * 8;
    const int laneRowB = (lane & 7) + ((lane >> 4) & 1) * 8;
    const int laneKB   = ((lane >> 3) & 1) * 8;

    float acc[MF][4][4];
#pragma unroll
    for (int i = 0; i < MF; i++)
#pragma unroll
        for (int j = 0; j < 4; j++)
#pragma unroll
            for (int v = 0; v < 4; v++) acc[i][j][v] = 0.f;

    const int NC = K >> 6;

    auto load_stage = [&](int c) {
        const int k0 = c << 6;
        const uint32_t sb = sbase + (uint32_t)(c % NS) * STAGE_B;
#pragma unroll
        for (int t = 0; t < 4; t++) {
            const __nv_bfloat16* S = srcs[t];
            const int ld    = (t < 2) ? lda : ldb;
            const int iters = ((t < 2 ? 128 : NT) * 8) / THREADS;
            const uint32_t poff = (t == 0) ? 0u : (t == 1) ? (uint32_t)PLANE_A
                                : (t == 2) ? (uint32_t)(2 * PLANE_A)
                                : (uint32_t)(2 * PLANE_A + PLANE_B);
#pragma unroll
            for (int j = 0; j < 4; j++) {
                if (j >= iters) break;
                const int idx = j * THREADS + tid;
                const int row = idx >> 3;
                const int c16 = idx & 7;
                const int gr  = (t < 2) ? min(row0 + row, M - 1) : (col0 + row);
                const void* src = S + (size_t)gr * ld + k0 + c16 * 8;
                cp_async16(sb + poff + row * ROWB + c16 * 16, src);
            }
        }
        cp_commit();
    };

#pragma unroll
    for (int s = 0; s < NS - 1; s++) {
        if (s < NC) load_stage(s); else cp_commit();
    }

    for (int c = 0; c < NC; c++) {
        cp_wait<NS - 2>();
        __syncthreads();
        if (c + NS - 1 < NC) load_stage(c + NS - 1); else cp_commit();

        const uint32_t sb = sbase + (uint32_t)(c % NS) * STAGE_B;
        const uint32_t aH = sb;
        const uint32_t aL = sb + PLANE_A;
        const uint32_t bH = sb + 2 * PLANE_A;
        const uint32_t bL = sb + 2 * PLANE_A + PLANE_B;

#pragma unroll
        for (int ks = 0; ks < 4; ks++) {
            uint32_t ah[MF][4], al[MF][4];
#pragma unroll
            for (int mf = 0; mf < MF; mf++) {
                const uint32_t off = (uint32_t)((wm * (MF * 16) + mf * 16 + laneRowA) * ROWB
                                                + (ks * 16 + laneKA) * 2);
                ldsm_x4(ah[mf], aH + off);
                ldsm_x4(al[mf], aL + off);
            }
            uint32_t bh[4][2], bl[4][2];
#pragma unroll
            for (int np = 0; np < 2; np++) {
                const uint32_t off = (uint32_t)((wn * 32 + np * 16 + laneRowB) * ROWB
                                                + (ks * 16 + laneKB) * 2);
                uint32_t th[4], tl[4];
                ldsm_x4(th, bH + off);
                ldsm_x4(tl, bL + off);
                bh[2 * np][0] = th[0]; bh[2 * np][1] = th[1];
                bh[2 * np + 1][0] = th[2]; bh[2 * np + 1][1] = th[3];
                bl[2 * np][0] = tl[0]; bl[2 * np][1] = tl[1];
                bl[2 * np + 1][0] = tl[2]; bl[2 * np + 1][1] = tl[3];
            }
#pragma unroll
            for (int mf = 0; mf < MF; mf++)
#pragma unroll
                for (int nf = 0; nf < 4; nf++) {
                    mma16816(acc[mf][nf], ah[mf], bh[nf][0], bh[nf][1]);
                    mma16816(acc[mf][nf], ah[mf], bl[nf][0], bl[nf][1]);
                    mma16816(acc[mf][nf], al[mf], bh[nf][0], bh[nf][1]);
                }
        }
    }
    __syncthreads();

#pragma unroll
    for (int mf = 0; mf < MF; mf++) {
#pragma unroll
        for (int half = 0; half < 2; half++) {
            const int r = row0 + wm * (MF * 16) + mf * 16 + (lane >> 2) + half * 8;
            if (r >= M) continue;
#pragma unroll
            for (int nf = 0; nf < 4; nf++) {
                const int cc = col0 + wn * 32 + nf * 8 + (lane & 3) * 2;
                const float v0 = acc[mf][nf][half * 2 + 0];
                const float v1 = acc[mf][nf][half * 2 + 1];
                if (EPI == 0) {
                    const float o0 = fmaxf(v0, 0.f);
                    const float o1 = fmaxf(v1, 0.f);
                    const __nv_bfloat16 h0 = __float2bfloat16(o0);
                    const __nv_bfloat16 h1 = __float2bfloat16(o1);
                    *(__nv_bfloat162*)(Chi + (size_t)r * 512 + cc) = __halves2bfloat162(h0, h1);
                    *(__nv_bfloat162*)(Clo + (size_t)r * 512 + cc) = __halves2bfloat162(
                        __float2bfloat16(o0 - __bfloat162float(h0)),
                        __float2bfloat16(o1 - __bfloat162float(h1)));
                } else {
                    *(float2*)(C + (size_t)r * ldc + cc) = make_float2(v0, v1);
                }
            }
        }
    }
}

template <int EPI, int NT, int NS, int THREADS>
__global__ __launch_bounds__(THREADS, 1)
void tgemm_k(const __nv_bfloat16* __restrict__ Ahi, const __nv_bfloat16* __restrict__ Alo,
             const __nv_bfloat16* __restrict__ Bhi, const __nv_bfloat16* __restrict__ Blo,
             float* __restrict__ C, __nv_bfloat16* Chi, __nv_bfloat16* Clo,
             int M, int K, int lda, int ldb, int ldc)
{
    extern __shared__ char dsm[];
    gemm_tile<EPI, NT, NS, THREADS>(Ahi, Alo, Bhi, Blo, C, Chi, Clo, M, K, lda, ldb, ldc,
                                    blockIdx.x * 128, blockIdx.y * NT, smem_u32(dsm));
}

// ---------------------------------------------------------------------------
// int8 GEMM: 128x128 tile, K-chunk 128 bytes, 3-product Ozaki, per-row scales.
// A: qAh/qAl [M][K] int8 + sA[row >> sshift]; B: qBh/qBl [512][K] + sB[n].
// EPI 0: relu -> bf16 hi/lo planes.  EPI 1: cand epilogue -> C fp32 (ldc 512).
// ---------------------------------------------------------------------------
template <int EPI>
__global__ __launch_bounds__(256, 1)
void igemm_k(const int8_t* __restrict__ qAh, const int8_t* __restrict__ qAl,
             const float* __restrict__ sA, int sshift,
             const int8_t* __restrict__ qBh, const int8_t* __restrict__ qBl,
             const float* __restrict__ sB,
             float* __restrict__ C, __nv_bfloat16* Chi, __nv_bfloat16* Clo,
             int M, int K,
             const float* __restrict__ biasc, const float* __restrict__ attn,
             const float* __restrict__ upd,
             const __nv_bfloat16* __restrict__ Lhi, const __nv_bfloat16* __restrict__ Llo)
{
    constexpr int NS = 3;
    constexpr int PLANE = 128 * ROWB;
    constexpr int STAGE_B = 4 * PLANE;
    extern __shared__ char dsm[];
    const uint32_t sbase = smem_u32(dsm);

    const int tid  = threadIdx.x;
    const int lane = tid & 31;
    const int wid  = tid >> 5;
    const int wm   = wid & 1;           // 2 M warps (64 rows each)
    const int wn   = wid >> 1;          // 4 N warps (32 cols each)
    const int row0 = blockIdx.x * 128;
    const int col0 = blockIdx.y * 128;

    const int8_t* srcs[4] = {qAh, qAl, qBh, qBl};

    const int laneRowA = (lane & 7) + ((lane >> 3) & 1) * 8;
    const int laneKAb  = ((lane >> 4) & 1) * 16;
    const int laneRowB = (lane & 7) + ((lane >> 4) & 1) * 8;
    const int laneKBb  = ((lane >> 3) & 1) * 16;

    int acc1[4][4][4], acc2[4][4][4];
#pragma unroll
    for (int i = 0; i < 4; i++)
#pragma unroll
        for (int j = 0; j < 4; j++)
#pragma unroll
            for (int v = 0; v < 4; v++) { acc1[i][j][v] = 0; acc2[i][j][v] = 0; }

    const int NC = K >> 7;              // 128-byte chunks

    auto load_stage = [&](int c) {
        const int k0 = c << 7;
        const uint32_t sb = sbase + (uint32_t)(c % NS) * STAGE_B;
#pragma unroll
        for (int t = 0; t < 4; t++) {
            const int8_t* S = srcs[t];
#pragma unroll
            for (int j = 0; j < 4; j++) {
                const int idx = j * 256 + tid;
                const int row = idx >> 3;
                const int c16 = idx & 7;
                const int gr  = (t < 2) ? min(row0 + row, M - 1) : (col0 + row);
                const void* src = S + (size_t)gr * K + k0 + c16 * 16;
                cp_async16(sb + (uint32_t)t * PLANE + row * ROWB + c16 * 16, src);
            }
        }
        cp_commit();
    };

#pragma unroll
    for (int s = 0; s < NS - 1; s++) {
        if (s < NC) load_stage(s); else cp_commit();
    }

    for (int c = 0; c < NC; c++) {
        cp_wait<NS - 2>();
        __syncthreads();
        if (c + NS - 1 < NC) load_stage(c + NS - 1); else cp_commit();

        const uint32_t sb = sbase + (uint32_t)(c % NS) * STAGE_B;
        const uint32_t aH = sb;
        const uint32_t aL = sb + PLANE;
        const uint32_t bH = sb + 2 * PLANE;
        const uint32_t bL = sb + 3 * PLANE;

#pragma unroll
        for (int ks = 0; ks < 4; ks++) {            // 4 x k32 sub-chunks
            uint32_t ah[4][4], al[4][4];
#pragma unroll
            for (int mf = 0; mf < 4; mf++) {
                const uint32_t off = (uint32_t)((wm * 64 + mf * 16 + laneRowA) * ROWB
                                                + ks * 32 + laneKAb);
                ldsm_x4(ah[mf], aH + off);
                ldsm_x4(al[mf], aL + off);
            }
            uint32_t bh[4][2], bl[4][2];
#pragma unroll
            for (int np = 0; np < 2; np++) {
                const uint32_t off = (uint32_t)((wn * 32 + np * 16 + laneRowB) * ROWB
                                                + ks * 32 + laneKBb);
                uint32_t th[4], tl[4];
                ldsm_x4(th, bH + off);
                ldsm_x4(tl, bL + off);
                bh[2 * np][0] = th[0]; bh[2 * np][1] = th[1];
                bh[2 * np + 1][0] = th[2]; bh[2 * np + 1][1] = th[3];
                bl[2 * np][0] = tl[0]; bl[2 * np][1] = tl[1];
                bl[2 * np + 1][0] = tl[2]; bl[2 * np + 1][1] = tl[3];
            }
#pragma unroll
            for (int mf = 0; mf < 4; mf++)
#pragma unroll
                for (int nf = 0; nf < 4; nf++) {
                    mma_s8(acc1[mf][nf], ah[mf], bh[nf][0], bh[nf][1]);
                    mma_s8(acc2[mf][nf], ah[mf], bl[nf][0], bl[nf][1]);
                    mma_s8(acc2[mf][nf], al[mf], bh[nf][0], bh[nf][1]);
                }
        }
    }
    __syncthreads();

#pragma unroll
    for (int mf = 0; mf < 4; mf++) {
#pragma unroll
        for (int half = 0; half < 2; half++) {
            const int r = row0 + wm * 64 + mf * 16 + (lane >> 2) + half * 8;
            if (r >= M) continue;
            const float sa = sA[r >> sshift];
            float g = 0.f;
            const float* bc = nullptr;
            if (EPI == 1) {
                g  = attn[r] * upd[r];
                bc = biasc + (size_t)(r >> 8) * 512;
            }
#pragma unroll
            for (int nf = 0; nf < 4; nf++) {
                const int cc = col0 + wn * 32 + nf * 8 + (lane & 3) * 2;
                const int i0 = half * 2;
                const float v0 = sa * sB[cc] *
                    (16384.f * (float)acc1[mf][nf][i0] + 128.f * (float)acc2[mf][nf][i0]);
                const float v1 = sa * sB[cc + 1] *
                    (16384.f * (float)acc1[mf][nf][i0 + 1] + 128.f * (float)acc2[mf][nf][i0 + 1]);
                if (EPI == 0) {
                    const float o0 = fmaxf(v0, 0.f);
                    const float o1 = fmaxf(v1, 0.f);
                    const __nv_bfloat16 h0 = __float2bfloat16(o0);
                    const __nv_bfloat16 h1 = __float2bfloat16(o1);
                    *(__nv_bfloat162*)(Chi + (size_t)r * 512 + cc) = __halves2bfloat162(h0, h1);
                    *(__nv_bfloat162*)(Clo + (size_t)r * 512 + cc) = __halves2bfloat162(
                        __float2bfloat16(o0 - __bfloat162float(h0)),
                        __float2bfloat16(o1 - __bfloat162float(h1)));
                } else {
                    const __nv_bfloat162 lh = *(const __nv_bfloat162*)(Lhi + (size_t)r * 512 + cc);
                    const __nv_bfloat162 ll = *(const __nv_bfloat162*)(Llo + (size_t)r * 512 + cc);
                    const float lf0 = __low2float(lh)  + __low2float(ll);
                    const float lf1 = __high2float(lh) + __high2float(ll);
                    const float o0 = g * sigf(v0 + bc[cc])     + (1.f - g) * lf0;
                    const float o1 = g * sigf(v1 + bc[cc + 1]) + (1.f - g) * lf1;
                    *(float2*)(C + (size_t)r * 512 + cc) = make_float2(o0, o1);
                }
            }
        }
    }
}

// ---------------------------------------------------------------------------
// grid barrier
// ---------------------------------------------------------------------------
__device__ __forceinline__ void grid_barrier(int nctas) {
    __syncthreads();
    if (threadIdx.x == 0) {
        __threadfence();
        const unsigned gen = *(volatile unsigned*)&g_bar_gen;
        if (atomicAdd(&g_bar_count, 1) == nctas - 1) {
            g_bar_count = 0;
            __threadfence();
            atomicAdd(&g_bar_gen, 1u);
        } else {
            while (*(volatile unsigned*)&g_bar_gen == gen) {}
            __threadfence();
        }
    }
    __syncthreads();
}

// ---------------------------------------------------------------------------
// persistent join kernel: levels 3..8 (bf16, K-split)
// ---------------------------------------------------------------------------
__global__ __launch_bounds__(256, 1)
void joinp_k(__nv_bfloat16* __restrict__ levhi, __nv_bfloat16* __restrict__ levlo,
             const __nv_bfloat16* __restrict__ Wjhi, const __nv_bfloat16* __restrict__ Wjlo)
{
    extern __shared__ char dsm[];
    const uint32_t sbase = smem_u32(dsm);

#pragma unroll 1
    for (int li = 0; li < 6; li++) {
        const int l    = li + 3;
        const int M    = 64 * (256 >> l);
        const int S    = c_S[li];
        const int Klen = 1024 / S;
        const int nsub = c_Mt[li] * 8 * S;

        const __nv_bfloat16* ahi = levhi + (size_t)c_roff[l - 1] * 512;
        const __nv_bfloat16* alo = levlo + (size_t)c_roff[l - 1] * 512;
        __nv_bfloat16* chi = levhi + (size_t)c_roff[l] * 512;
        __nv_bfloat16* clo = levlo + (size_t)c_roff[l] * 512;

        const int st = blockIdx.x;
        if (st < nsub) {
            const int sp = st % S;
            const int t2 = st / S;
            const int nt = t2 & 7;
            const int mt = t2 >> 3;
            if (S == 1) {
                gemm_tile<0, 64, 4, 256>(ahi, alo, Wjhi, Wjlo, nullptr, chi, clo,
                                         M, 1024, 1024, 1024, 512,
                                         mt * 128, nt * 64, sbase);
            } else {
                float* Cp = g_part + (size_t)st * 8192 - (size_t)mt * 128 * 64;
                gemm_tile<2, 64, 4, 256>(ahi + sp * Klen, alo + sp * Klen,
                                         Wjhi + (size_t)(nt * 64) * 1024 + sp * Klen,
                                         Wjlo + (size_t)(nt * 64) * 1024 + sp * Klen,
                                         Cp, nullptr, nullptr,
                                         M, Klen, 1024, 1024, 64,
                                         mt * 128, 0, sbase);
            }
        }
        grid_barrier(gridDim.x);

        if (S > 1) {
            const int total = M * 512;
            for (int idx = blockIdx.x * 256 + threadIdx.x; idx < total;
                 idx += gridDim.x * 256) {
                const int r  = idx >> 9;
                const int c  = idx & 511;
                const int mt = r >> 7;
                const int nt = c >> 6;
                const size_t base = (size_t)((mt * 8 + nt) * S) * 8192
                                    + (r & 127) * 64 + (c & 63);
                float v = 0.f;
                for (int p = 0; p < S; p++) v += g_part[base + (size_t)p * 8192];
                v = fmaxf(v, 0.f);
                const __nv_bfloat16 h = __float2bfloat16(v);
                chi[(size_t)r * 512 + c] = h;
                clo[(size_t)r * 512 + c] = __float2bfloat16(v - __bfloat162float(h));
            }
            grid_barrier(gridDim.x);
        }
    }
}

// ---------------------------------------------------------------------------
// LSTM z GEMM, K-split x4 (bf16)
// ---------------------------------------------------------------------------
__global__ __launch_bounds__(256, 1)
void lstmgemm_k(const __nv_bfloat16* __restrict__ zAhi, const __nv_bfloat16* __restrict__ zAlo,
                const __nv_bfloat16* __restrict__ Bzhi, const __nv_bfloat16* __restrict__ Bzlo)
{
    extern __shared__ char dsm[];
    const int s  = blockIdx.x;
    const int nt = blockIdx.y;
    gemm_tile<2, 64, 4, 256>(zAhi + s * 256, zAlo + s * 256,
                             Bzhi + s * 256, Bzlo + s * 256,
                             g_z4 + (size_t)s * (BSZ * 2048), nullptr, nullptr,
                             64, 256, 1024, 1024, 2048,
                             0, nt * 64, smem_u32(dsm));
}

// ---------------------------------------------------------------------------
// prep: input int8 quant + weight int8 quant + Wj/kern/rec bf16 + ctrl + biasc
// ---------------------------------------------------------------------------
__device__ __forceinline__ void wsplit_body(const float* __restrict__ W,
                                            __nv_bfloat16* __restrict__ H,
                                            __nv_bfloat16* __restrict__ L,
                                            int Nsrc, int ldK, int koff,
                                            int bx, int by, float* shbuf)
{
    float (*t)[33] = (float(*)[33])shbuf;
    const int k0 = bx * 32, n0 = by * 32;
    const int tx = threadIdx.x & 31, ty = threadIdx.x >> 5;
    for (int r = ty; r < 32; r += 8)
        t[r][tx] = W[(size_t)(k0 + r) * Nsrc + n0 + tx];
    __syncthreads();
    for (int r = ty; r < 32; r += 8) {
        const float x = t[tx][r];
        const __nv_bfloat16 h = __float2bfloat16(x);
        H[(size_t)(n0 + r) * ldK + koff + k0 + tx] = h;
        L[(size_t)(n0 + r) * ldK + koff + k0 + tx] = __float2bfloat16(x - __bfloat162float(h));
    }
}

// warp: quantize one weight n-row (W[k][n], k<K) -> qh/ql[n][K], sW[n]
__device__ __forceinline__ void wquant_body(const float* __restrict__ W,
                                            int8_t* __restrict__ qh, int8_t* __restrict__ ql,
                                            float* __restrict__ sW, int K, int n)
{
    const int lane = threadIdx.x & 31;
    float m = 0.f;
    for (int i = 0; i < K / 32; i++)
        m = fmaxf(m, fabsf(W[(size_t)(lane + i * 32) * 512 + n]));
    m = warp_max(m);
    const float amax = fmaxf(m, 1e-30f);
    const float inv  = 16256.f / amax;
    if (lane == 0) sW[n] = amax / 16256.f;
    const int len = K / 32;             // 16 or 32
    const int kk0 = lane * len;
    int8_t hb[32], lb[32];
    for (int j = 0; j < len; j++)
        quant2(W[(size_t)(kk0 + j) * 512 + n], inv, hb[j], lb[j]);
    for (int ofs = 0; ofs < len; ofs += 16) {
        *(int4*)(qh + (size_t)n * K + kk0 + ofs) = *(int4*)(hb + ofs);
        *(int4*)(ql + (size_t)n * K + kk0 + ofs) = *(int4*)(lb + ofs);
    }
}

__global__ __launch_bounds__(256)
void prep_k(const float* __restrict__ inputs,
            const float* __restrict__ h0,
            const float* __restrict__ W_t, const float* __restrict__ W_j,
            const float* __restrict__ W_s, const float* __restrict__ W_h,
            const float* __restrict__ W_T,
            const float* __restrict__ kern, const float* __restrict__ rec)
{
    __shared__ float shbuf[32 * 33];
    const int blk = blockIdx.x;
    const int tid = threadIdx.x;
    const int lane = tid & 31;
    const int w = tid >> 5;

    if (blk < 2048) {
        // input quant: warp per row
        const int row = blk * 8 + w;
        const float* xr = inputs + (size_t)row * 512 + lane * 16;
        float x[16];
#pragma unroll
        for (int i = 0; i < 4; i++) {
            const float4 v = *(const float4*)(xr + i * 4);
            x[4 * i] = v.x; x[4 * i + 1] = v.y; x[4 * i + 2] = v.z; x[4 * i + 3] = v.w;
        }
        float m = 0.f;
#pragma unroll
        for (int i = 0; i < 16; i++) m = fmaxf(m, fabsf(x[i]));
        m = warp_max(m);
        const float amax = fmaxf(m, 1e-30f);
        const float inv  = 16256.f / amax;
        if (lane == 0) g_sA[row] = amax / 16256.f;
        int8_t hb[16], lb[16];
#pragma unroll
        for (int i = 0; i < 16; i++) quant2(x[i], inv, hb[i], lb[i]);
        *(int4*)(g_qAh + (size_t)row * 512 + lane * 16) = *(int4*)hb;
        *(int4*)(g_qAl + (size_t)row * 512 + lane * 16) = *(int4*)lb;
    } else if (blk < 2112) {
        wquant_body(W_t, g_qWth, g_qWtl, g_sWt, 512, (blk - 2048) * 8 + w);
    } else if (blk < 2176) {
        wquant_body(W_h, g_qWhh, g_qWhl, g_sWh, 512, (blk - 2112) * 8 + w);
    } else if (blk < 2240) {
        wquant_body(W_j, g_qWjh, g_qWjl, g_sWj, 1024, (blk - 2176) * 8 + w);
    } else if (blk < 2752) {
        const int j = blk - 2240;                                // Wj bf16: 32 x 16
        wsplit_body(W_j, g_Wjhi, g_Wjlo, 512, 1024, 0, j % 32, j / 32, shbuf);
    } else if (blk < 3776) {
        const int j = blk - 2752;                                // kern: 16 x 64
        wsplit_body(kern, g_Bzhi, g_Bzlo, 2048, 1024, 0, j % 16, j / 16, shbuf);
    } else if (blk < 4800) {
        const int j = blk - 3776;                                // rec
        wsplit_body(rec, g_Bzhi, g_Bzlo, 2048, 1024, 512, j % 16, j / 16, shbuf);
    } else if (blk < 4864) {
        const int b = blk - 4800;
        if (w < 2) {
            const float* wv = (w == 0 ? W_s : W_T) + 512;
            const float* hr = h0 + b * 512;
            float s = 0.f;
#pragma unroll
            for (int i = 0; i < 16; i++) s = fmaf(hr[lane + i * 32], wv[lane + i * 32], s);
#pragma unroll
            for (int o = 16; o; o >>= 1) s += __shfl_xor_sync(0xffffffffu, s, o);
            if (lane == 0) { if (w == 0) g_sctrl[b] = s; else g_tctrl[b] = s; }
        }
    } else {
        const int b = blk - 4864;
        float* sh = shbuf;
        sh[tid]       = h0[b * 512 + tid];
        sh[tid + 256] = h0[b * 512 + tid + 256];
        __syncthreads();
        const float* wp = W_h + (size_t)512 * 512 + tid;
        float a0 = 0.f, a1 = 0.f;
#pragma unroll 16
        for (int u = 0; u < 512; u++) {
            const float hv = sh[u];
            a0 = fmaf(hv, wp[(size_t)u * 512], a0);
            a1 = fmaf(hv, wp[(size_t)u * 512 + 256], a1);
        }
        g_biasc[b * 512 + tid]       = a0;
        g_biasc[b * 512 + tid + 256] = a1;
    }
}

// ---------------------------------------------------------------------------
// leaf quant: warp per leaf PAIR (1024 elems, shared scale) from bf16 planes
// ---------------------------------------------------------------------------
__global__ __launch_bounds__(256)
void leafq_k()
{
    const int p = blockIdx.x * 8 + (threadIdx.x >> 5);
    const int lane = threadIdx.x & 31;
    const int row = 2 * p + (lane >> 4);
    const int cb  = (lane & 15) * 32;
    const __nv_bfloat162* ph = (const __nv_bfloat162*)(g_leafhi + (size_t)row * 512 + cb);
    const __nv_bfloat162* pl = (const __nv_bfloat162*)(g_leaflo + (size_t)row * 512 + cb);
    float vals[32];
    float m = 0.f;
#pragma unroll
    for (int i = 0; i < 16; i++) {
        const __nv_bfloat162 h2 = ph[i];
        const __nv_bfloat162 l2 = pl[i];
        vals[2 * i]     = __low2float(h2)  + __low2float(l2);
        vals[2 * i + 1] = __high2float(h2) + __high2float(l2);
        m = fmaxf(m, fmaxf(fabsf(vals[2 * i]), fabsf(vals[2 * i + 1])));
    }
    m = warp_max(m);
    const float amax = fmaxf(m, 1e-30f);
    const float inv  = 16256.f / amax;
    if (lane == 0) g_sLP[p] = amax / 16256.f;
    int8_t hb[32], lb[32];
#pragma unroll
    for (int i = 0; i < 32; i++) quant2(vals[i], inv, hb[i], lb[i]);
    *(int4*)(g_qLh + (size_t)row * 512 + cb)      = *(int4*)hb;
    *(int4*)(g_qLh + (size_t)row * 512 + cb + 16) = *(int4*)(hb + 16);
    *(int4*)(g_qLl + (size_t)row * 512 + cb)      = *(int4*)lb;
    *(int4*)(g_qLl + (size_t)row * 512 + cb + 16) = *(int4*)(lb + 16);
}

// ---------------------------------------------------------------------------
// small kernels (unchanged)
// ---------------------------------------------------------------------------
__global__ __launch_bounds__(256)
void mrupd_k(const float* __restrict__ Ws, const float* __restrict__ WT)
{
    const int gw   = blockIdx.x * 8 + (threadIdx.x >> 5);
    const int lane = threadIdx.x & 31;

    const __nv_bfloat162* hi;
    const __nv_bfloat162* lo;
    const float2* wv;
    if (gw < 16384) {
        hi = (const __nv_bfloat162*)(g_leafhi + (size_t)gw * 512);
        lo = (const __nv_bfloat162*)(g_leaflo + (size_t)gw * 512);
        wv = (const float2*)WT;
    } else {
        const int node = gw - 16384;
        if (node >= 16320) return;
        hi = (const __nv_bfloat162*)(g_levhi + (size_t)node * 512);
        lo = (const __nv_bfloat162*)(g_levlo + (size_t)node * 512);
        wv = (const float2*)Ws;
    }
    float s = 0.f;
#pragma unroll
    for (int i = 0; i < 8; i++) {
        const int idx = lane + i * 32;
        const __nv_bfloat162 h2 = hi[idx];
        const __nv_bfloat162 l2 = lo[idx];
        const float2 w = wv[idx];
        s = fmaf(__low2float(h2)  + __low2float(l2),  w.x, s);
        s = fmaf(__high2float(h2) + __high2float(l2), w.y, s);
    }
#pragma unroll
    for (int o = 16; o; o >>= 1) s += __shfl_xor_sync(0xffffffffu, s, o);
    if (lane == 0) {
        if (gw < 16384) {
            g_upd[gw] = sigf(s + g_tctrl[gw >> 8]);
        } else {
            const int node = gw - 16384;
            int l = 1;
#pragma unroll
            for (int t = 2; t <= 8; t++)
                if (node >= c_roff[t]) l = t;
            const int m = 256 >> l;
            const int b = (node - c_roff[l]) / m;
            g_mr[node] = sigf(s + g_sctrl[b]);
        }
    }
}

__global__ void attn_k()
{
    __shared__ float sa[2][256];
    const int b = blockIdx.x, t = threadIdx.x;
    if (t == 0) sa[0][0] = 1.f;
    __syncthreads();
    int cur = 0;
    for (int l = 8; l >= 1; --l) {
        const int m = 256 >> l;
        if (t < m) {
            const float a  = sa[cur][t];
            const float mv = g_mr[c_roff[l] + b * m + t];
            sa[cur ^ 1][2 * t]     = a * (1.f - mv);
            sa[cur ^ 1][2 * t + 1] = a * mv;
        }
        __syncthreads();
        cur ^= 1;
    }
    g_attn[b * 256 + t]       = sa[cur][t];
    g_attn[b * 256 + 128 + t] = sa[cur][128 + t];
}

__global__ __launch_bounds__(512) void treeoutz_k(const float* __restrict__ inputs,
                                                  const float* __restrict__ h0)
{
    __shared__ float sat[256];
    const int b = blockIdx.x, t = threadIdx.x;
    if (t < 256) sat[t] = g_attn[b * 256 + t];
    __syncthreads();
    float a0 = 0.f, a1 = 0.f, a2 = 0.f, a3 = 0.f;
    const float* ip = inputs + (size_t)b * 256 * 512 + t;
#pragma unroll 4
    for (int n = 0; n < 256; n += 4) {
        a0 = fmaf(sat[n],     ip[(size_t)n * 512],       a0);
        a1 = fmaf(sat[n + 1], ip[(size_t)(n + 1) * 512], a1);
        a2 = fmaf(sat[n + 2], ip[(size_t)(n + 2) * 512], a2);
        a3 = fmaf(sat[n + 3], ip[(size_t)(n + 3) * 512], a3);
    }
    const float acc = (a0 + a1) + (a2 + a3);
    const __nv_bfloat16 th = __float2bfloat16(acc);
    g_zAhi[b * 1024 + t] = th;
    g_zAlo[b * 1024 + t] = __float2bfloat16(acc - __bfloat162float(th));
    const float hv = h0[b * 512 + t];
    const __nv_bfloat16 hh = __float2bfloat16(hv);
    g_zAhi[b * 1024 + 512 + t] = hh;
    g_zAlo[b * 1024 + 512 + t] = __float2bfloat16(hv - __bfloat162float(hh));
}

__global__ __launch_bounds__(512) void gate_k(
    const float* __restrict__ c0, const float* __restrict__ bias,
    float* __restrict__ hout, float* __restrict__ cout)
{
    const int b = blockIdx.x, u = threadIdx.x;
    const size_t zo0 = (size_t)b * 2048;
    const float zi = g_z4[zo0 + u]        + g_z4[131072 + zo0 + u]
                   + g_z4[262144 + zo0 + u] + g_z4[393216 + zo0 + u] + bias[u];
    const float zf = g_z4[zo0 + 512 + u]  + g_z4[131072 + zo0 + 512 + u]
                   + g_z4[262144 + zo0 + 512 + u] + g_z4[393216 + zo0 + 512 + u] + bias[512 + u];
    const float zg = g_z4[zo0 + 1024 + u] + g_z4[131072 + zo0 + 1024 + u]
                   + g_z4[262144 + zo0 + 1024 + u] + g_z4[393216 + zo0 + 1024 + u] + bias[1024 + u];
    const float zo = g_z4[zo0 + 1536 + u] + g_z4[131072 + zo0 + 1536 + u]
                   + g_z4[262144 + zo0 + 1536 + u] + g_z4[393216 + zo0 + 1536 + u] + bias[1536 + u];
    const float cn = sigf(zf) * c0[b * 512 + u] + sigf(zi) * tanhf(zg);
    hout[b * 512 + u] = sigf(zo) * tanhf(cn);
    cout[b * 512 + u] = cn;
}

// ---------------------------------------------------------------------------
extern "C" void kernel_launch(void* const* d_in, const int* in_sizes, int n_in,
                              void* d_out, int out_size)
{
    const float* inputs = (const float*)d_in[0];
    const float* h0     = (const float*)d_in[1];
    const float* c0     = (const float*)d_in[2];
    const float* W_t    = (const float*)d_in[3];
    const float* W_j    = (const float*)d_in[4];
    const float* W_s    = (const float*)d_in[5];
    const float* W_h    = (const float*)d_in[6];
    const float* W_T    = (const float*)d_in[7];
    const float* kern   = (const float*)d_in[8];
    const float* rec    = (const float*)d_in[9];
    const float* bias   = (const float*)d_in[10];

    float* out      = (float*)d_out;
    float* h_new    = out;
    float* c_new    = out + BSZ * UD;
    float* leaf_new = out + 2 * BSZ * UD;

    float *p_biasc, *p_attn, *p_upd, *p_sA, *p_sLP, *p_sWt, *p_sWh, *p_sWj;
    __nv_bfloat16 *p_leafhi, *p_leaflo, *p_levhi, *p_levlo;
    __nv_bfloat16 *p_Wjhi, *p_Wjlo, *p_Bzhi, *p_Bzlo, *p_zAhi, *p_zAlo;
    int8_t *p_qAh, *p_qAl, *p_qLh, *p_qLl, *p_qWth, *p_qWtl, *p_qWhh, *p_qWhl, *p_qWjh, *p_qWjl;
    cudaGetSymbolAddress((void**)&p_biasc,  g_biasc);
    cudaGetSymbolAddress((void**)&p_attn,   g_attn);
    cudaGetSymbolAddress((void**)&p_upd,    g_upd);
    cudaGetSymbolAddress((void**)&p_leafhi, g_leafhi);
    cudaGetSymbolAddress((void**)&p_leaflo, g_leaflo);
    cudaGetSymbolAddress((void**)&p_levhi,  g_levhi);
    cudaGetSymbolAddress((void**)&p_levlo,  g_levlo);
    cudaGetSymbolAddress((void**)&p_Wjhi,   g_Wjhi);
    cudaGetSymbolAddress((void**)&p_Wjlo,   g_Wjlo);
    cudaGetSymbolAddress((void**)&p_Bzhi,   g_Bzhi);
    cudaGetSymbolAddress((void**)&p_Bzlo,   g_Bzlo);
    cudaGetSymbolAddress((void**)&p_zAhi,   g_zAhi);
    cudaGetSymbolAddress((void**)&p_zAlo,   g_zAlo);
    cudaGetSymbolAddress((void**)&p_qAh,    g_qAh);
    cudaGetSymbolAddress((void**)&p_qAl,    g_qAl);
    cudaGetSymbolAddress((void**)&p_qLh,    g_qLh);
    cudaGetSymbolAddress((void**)&p_qLl,    g_qLl);
    cudaGetSymbolAddress((void**)&p_qWth,   g_qWth);
    cudaGetSymbolAddress((void**)&p_qWtl,   g_qWtl);
    cudaGetSymbolAddress((void**)&p_qWhh,   g_qWhh);
    cudaGetSymbolAddress((void**)&p_qWhl,   g_qWhl);
    cudaGetSymbolAddress((void**)&p_qWjh,   g_qWjh);
    cudaGetSymbolAddress((void**)&p_qWjl,   g_qWjl);
    cudaGetSymbolAddress((void**)&p_sA,     g_sA);
    cudaGetSymbolAddress((void**)&p_sLP,    g_sLP);
    cudaGetSymbolAddress((void**)&p_sWt,    g_sWt);
    cudaGetSymbolAddress((void**)&p_sWh,    g_sWh);
    cudaGetSymbolAddress((void**)&p_sWj,    g_sWj);

    cudaFuncSetAttribute((const void*)igemm_k<0>,
                         cudaFuncAttributeMaxDynamicSharedMemorySize, SMEM_128);
    cudaFuncSetAttribute((const void*)igemm_k<1>,
                         cudaFuncAttributeMaxDynamicSharedMemorySize, SMEM_128);
    cudaFuncSetAttribute((const void*)tgemm_k<0, 128, 3, 256>,
                         cudaFuncAttributeMaxDynamicSharedMemorySize, SMEM_128);
    cudaFuncSetAttribute((const void*)joinp_k,
                         cudaFuncAttributeMaxDynamicSharedMemorySize, SMEM_64);
    cudaFuncSetAttribute((const void*)lstmgemm_k,
                         cudaFuncAttributeMaxDynamicSharedMemorySize, SMEM_64);

    // 1: quantization + bf16 weight planes + ctrl + biasc
    prep_k<<<4928, 256>>>(inputs, h0, W_t, W_j, W_s, W_h, W_T, kern, rec);

    // 2: leaf embed (int8): relu(inputs @ W_t) -> bf16 leaf planes
    igemm_k<0><<<dim3(128, 4), 256, SMEM_128>>>(
        p_qAh, p_qAl, p_sA, 0, p_qWth, p_qWtl, p_sWt,
        nullptr, p_leafhi, p_leaflo, 16384, 512,
        nullptr, nullptr, nullptr, nullptr, nullptr);

    // 3: leaf pair quantization -> qL + sLP
    leafq_k<<<1024, 256>>>();

    // 4: join level 1 (int8): leaf pairs @ W_j -> bf16 lev1 planes
    igemm_k<0><<<dim3(64, 4), 256, SMEM_128>>>(
        p_qLh, p_qLl, p_sLP, 0, p_qWjh, p_qWjl, p_sWj,
        nullptr, p_levhi + (size_t)h_roff[1] * 512, p_levlo + (size_t)h_roff[1] * 512,
        8192, 1024, nullptr, nullptr, nullptr, nullptr, nullptr);

    // 5: join level 2 (bf16)
    tgemm_k<0, 128, 3, 256><<<dim3(32, 4), 256, SMEM_128>>>(
        p_levhi + (size_t)h_roff[1] * 512, p_levlo + (size_t)h_roff[1] * 512,
        p_Wjhi, p_Wjlo, nullptr,
        p_levhi + (size_t)h_roff[2] * 512, p_levlo + (size_t)h_roff[2] * 512,
        4096, 1024, 1024, 1024, 512);

    // 6: join levels 3-8 (bf16, persistent K-split)
    joinp_k<<<148, 256, SMEM_64>>>(p_levhi, p_levlo, p_Wjhi, p_Wjlo);

    // 7-9: gates, attention, tree_out
    mrupd_k<<<4088, 256>>>(W_s, W_T);
    attn_k<<<64, 128>>>();
    treeoutz_k<<<64, 512>>>(inputs, h0);

    // 10: cand GEMM (int8) -> leaf_new
    igemm_k<1><<<dim3(128, 4), 256, SMEM_128>>>(
        p_qLh, p_qLl, p_sLP, 1, p_qWhh, p_qWhl, p_sWh,
        leaf_new, nullptr, nullptr, 16384, 512,
        p_biasc, p_attn, p_upd, p_leafhi, p_leaflo);

    // 11: LSTM z GEMM (bf16, K-split x4)
    lstmgemm_k<<<dim3(4, 32), 256, SMEM_64>>>(p_zAhi, p_zAlo, p_Bzhi, p_Bzlo);

    // 12: gates
    gate_k<<<64, 512>>>(c0, bias, h_new, c_new);
}

// round 13
// speedup vs baseline: 1.8062x; 1.8062x over previous
#include <cuda_runtime.h>
#include <cuda_bf16.h>
#include <cstdint>
#include <math.h>

#define BSZ   64
#define NLEAF 256
#define ED    512
#define DD    512
#define UD    512

// ---------------------------------------------------------------------------
// scratch (device globals; no allocation allowed)
// ---------------------------------------------------------------------------
__device__ __nv_bfloat16 g_Ahi   [BSZ * NLEAF * ED];
__device__ __nv_bfloat16 g_Alo   [BSZ * NLEAF * ED];
__device__ __nv_bfloat16 g_leafhi[BSZ * NLEAF * DD];
__device__ __nv_bfloat16 g_leaflo[BSZ * NLEAF * DD];
__device__ __nv_bfloat16 g_levhi [BSZ * 255  * DD];
__device__ __nv_bfloat16 g_levlo [BSZ * 255  * DD];
__device__ __nv_bfloat16 g_Wthi[512 * 512],  g_Wtlo[512 * 512];   // [n][k]
__device__ __nv_bfloat16 g_Wjhi[512 * 1024], g_Wjlo[512 * 1024];  // [n][k]
__device__ __nv_bfloat16 g_Whhi[512 * 512],  g_Whlo[512 * 512];   // [n][k]
__device__ __nv_bfloat16 g_Bzhi[2048 * 1024], g_Bzlo[2048 * 1024];// [n][k] (kern;rec)
__device__ __nv_bfloat16 g_zAhi[BSZ * 1024],  g_zAlo[BSZ * 1024]; // [tree|h0]
__device__ float g_z4    [4 * BSZ * 2048];     // LSTM K-split partials
__device__ float g_part  [128 * 128 * 64];     // join K-split partials (4MB)
__device__ float g_mr    [BSZ * 255];
__device__ float g_attn  [BSZ * NLEAF];
__device__ float g_sctrl [BSZ];
__device__ float g_tctrl [BSZ];
__device__ float g_biasc [BSZ * DD];
__device__ float g_upd   [BSZ * NLEAF];
__device__ int      g_bar_count;
__device__ unsigned g_bar_gen;

__constant__ int c_roff[9] = {0, 0, 8192, 12288, 14336, 15360, 15872, 16128, 16256};
__constant__ int c_Mt[6] = {16, 8, 4, 2, 1, 1};   // M-tiles per level 3..8
__constant__ int c_S [6] = {1,  2, 4, 8, 8, 8};   // K-splits per level 3..8
static const int h_roff[9] = {0, 0, 8192, 12288, 14336, 15360, 15872, 16128, 16256};

__device__ __forceinline__ float sigf(float x) { return 1.f / (1.f + __expf(-x)); }

__device__ __forceinline__ uint32_t smem_u32(const void* p) {
    uint32_t a;
    asm("{ .reg .u64 t; cvta.to.shared.u64 t, %1; cvt.u32.u64 %0, t; }" : "=r"(a) : "l"(p));
    return a;
}

__device__ __forceinline__ void cp_async16(uint32_t dst, const void* src) {
    asm volatile("cp.async.cg.shared.global [%0], [%1], 16;" :: "r"(dst), "l"(src));
}
__device__ __forceinline__ void cp_commit() {
    asm volatile("cp.async.commit_group;" ::: "memory");
}
template <int N>
__device__ __forceinline__ void cp_wait() {
    asm volatile("cp.async.wait_group %0;" :: "n"(N) : "memory");
}

__device__ __forceinline__ void ldsm_x4(uint32_t (&r)[4], uint32_t addr) {
    asm volatile("ldmatrix.sync.aligned.m8n8.x4.shared.b16 {%0,%1,%2,%3}, [%4];"
                 : "=r"(r[0]), "=r"(r[1]), "=r"(r[2]), "=r"(r[3]) : "r"(addr));
}

__device__ __forceinline__ void mma16816(float (&d)[4], const uint32_t (&a)[4],
                                         uint32_t b0, uint32_t b1) {
    asm volatile(
        "mma.sync.aligned.m16n8k16.row.col.f32.bf16.bf16.f32 "
        "{%0,%1,%2,%3},{%4,%5,%6,%7},{%8,%9},{%0,%1,%2,%3};"
        : "+f"(d[0]), "+f"(d[1]), "+f"(d[2]), "+f"(d[3])
        : "r"(a[0]), "r"(a[1]), "r"(a[2]), "r"(a[3]), "r"(b0), "r"(b1));
}

// ---------------------------------------------------------------------------
// GEMM tile body: one 128 x NT tile of C = A @ B (3-product fp32 emulation).
// A: bf16 hi/lo, row stride lda; B: bf16 hi/lo [n][k], row stride ldb.
// ---------------------------------------------------------------------------
#define ROWB 144

template <int EPI, int NT, int NS, int THREADS>
__device__ __forceinline__ void gemm_tile(
    const __nv_bfloat16* __restrict__ Ahi, const __nv_bfloat16* __restrict__ Alo,
    const __nv_bfloat16* __restrict__ Bhi, const __nv_bfloat16* __restrict__ Blo,
    float* __restrict__ C, __nv_bfloat16* Chi, __nv_bfloat16* Clo,
    int M, int K, int lda, int ldb, int ldc,
    const float* __restrict__ biasc, const float* __restrict__ attn,
    const float* __restrict__ upd,
    int row0, int col0, uint32_t sbase)
{
    constexpr int PLANE_A = 128 * ROWB;
    constexpr int PLANE_B = NT * ROWB;
    constexpr int STAGE_B = 2 * PLANE_A + 2 * PLANE_B;
    constexpr int NWARPS  = THREADS / 32;
    constexpr int NWN     = NT / 32;
    constexpr int NWM     = NWARPS / NWN;
    constexpr int MF      = 128 / (16 * NWM);
    static_assert(NWM * NWN == NWARPS && MF >= 1, "bad layout");

    const int tid  = threadIdx.x;
    const int lane = tid & 31;
    const int wid  = tid >> 5;
    const int wm   = wid % NWM;
    const int wn   = wid / NWM;

    const __nv_bfloat16* srcs[4] = {Ahi, Alo, Bhi, Blo};

    const int laneRowA = (lane & 7) + ((lane >> 3) & 1) * 8;
    const int laneKA   = ((lane >> 4) & 1) * 8;
    const int laneRowB = (lane & 7) + ((lane >> 4) & 1) * 8;
    const int laneKB   = ((lane >> 3) & 1) * 8;

    float acc[MF][4][4];
#pragma unroll
    for (int i = 0; i < MF; i++)
#pragma unroll
        for (int j = 0; j < 4; j++)
#pragma unroll
            for (int v = 0; v < 4; v++) acc[i][j][v] = 0.f;

    const int NC = K >> 6;

    auto load_stage = [&](int c) {
        const int k0 = c << 6;
        const uint32_t sb = sbase + (uint32_t)(c % NS) * STAGE_B;
#pragma unroll
        for (int t = 0; t < 4; t++) {
            const __nv_bfloat16* S = srcs[t];
            const int ld    = (t < 2) ? lda : ldb;
            const int iters = ((t < 2 ? 128 : NT) * 8) / THREADS;
            const uint32_t poff = (t == 0) ? 0u : (t == 1) ? (uint32_t)PLANE_A
                                : (t == 2) ? (uint32_t)(2 * PLANE_A)
                                : (uint32_t)(2 * PLANE_A + PLANE_B);
#pragma unroll
            for (int j = 0; j < 4; j++) {
                if (j >= iters) break;
                const int idx = j * THREADS + tid;
                const int row = idx >> 3;
                const int c16 = idx & 7;
                const int gr  = (t < 2) ? min(row0 + row, M - 1) : (col0 + row);
                const void* src = S + (size_t)gr * ld + k0 + c16 * 8;
                cp_async16(sb + poff + row * ROWB + c16 * 16, src);
            }
        }
        cp_commit();
    };

    // preload NS-1 groups (empty commits pad the count)
#pragma unroll
    for (int s = 0; s < NS - 1; s++) {
        if (s < NC) load_stage(s); else cp_commit();
    }

    for (int c = 0; c < NC; c++) {
        cp_wait<NS - 2>();              // oldest pending group (chunk c) done
        __syncthreads();                // + all warps released buf (c-1)%NS
        if (c + NS - 1 < NC) load_stage(c + NS - 1); else cp_commit();

        const uint32_t sb = sbase + (uint32_t)(c % NS) * STAGE_B;
        const uint32_t aH = sb;
        const uint32_t aL = sb + PLANE_A;
        const uint32_t bH = sb + 2 * PLANE_A;
        const uint32_t bL = sb + 2 * PLANE_A + PLANE_B;

#pragma unroll
        for (int ks = 0; ks < 4; ks++) {
            uint32_t ah[MF][4], al[MF][4];
#pragma unroll
            for (int mf = 0; mf < MF; mf++) {
                const uint32_t off = (uint32_t)((wm * (MF * 16) + mf * 16 + laneRowA) * ROWB
                                                + (ks * 16 + laneKA) * 2);
                ldsm_x4(ah[mf], aH + off);
                ldsm_x4(al[mf], aL + off);
            }
            uint32_t bh[4][2], bl[4][2];
#pragma unroll
            for (int np = 0; np < 2; np++) {
                const uint32_t off = (uint32_t)((wn * 32 + np * 16 + laneRowB) * ROWB
                                                + (ks * 16 + laneKB) * 2);
                uint32_t th[4], tl[4];
                ldsm_x4(th, bH + off);
                ldsm_x4(tl, bL + off);
                bh[2 * np][0] = th[0]; bh[2 * np][1] = th[1];
                bh[2 * np + 1][0] = th[2]; bh[2 * np + 1][1] = th[3];
                bl[2 * np][0] = tl[0]; bl[2 * np][1] = tl[1];
                bl[2 * np + 1][0] = tl[2]; bl[2 * np + 1][1] = tl[3];
            }
#pragma unroll
            for (int mf = 0; mf < MF; mf++)
#pragma unroll
                for (int nf = 0; nf < 4; nf++) {
                    mma16816(acc[mf][nf], ah[mf], bh[nf][0], bh[nf][1]);
                    mma16816(acc[mf][nf], ah[mf], bl[nf][0], bl[nf][1]);
                    mma16816(acc[mf][nf], al[mf], bh[nf][0], bh[nf][1]);
                }
        }
    }
    __syncthreads();                    // release buffers before epilogue/reuse

#pragma unroll
    for (int mf = 0; mf < MF; mf++) {
#pragma unroll
        for (int half = 0; half < 2; half++) {
            const int r = row0 + wm * (MF * 16) + mf * 16 + (lane >> 2) + half * 8;
            if (r >= M) continue;
            float g = 0.f;
            const float* bc = nullptr;
            if (EPI == 1) {
                g  = attn[r] * upd[r];
                bc = biasc + (size_t)(r >> 8) * 512;
            }
#pragma unroll
            for (int nf = 0; nf < 4; nf++) {
                const int cc = col0 + wn * 32 + nf * 8 + (lane & 3) * 2;
                const float v0 = acc[mf][nf][half * 2 + 0];
                const float v1 = acc[mf][nf][half * 2 + 1];
                if (EPI == 0) {
                    const float o0 = fmaxf(v0, 0.f);
                    const float o1 = fmaxf(v1, 0.f);
                    const __nv_bfloat16 h0 = __float2bfloat16(o0);
                    const __nv_bfloat16 h1 = __float2bfloat16(o1);
                    *(__nv_bfloat162*)(Chi + (size_t)r * 512 + cc) = __halves2bfloat162(h0, h1);
                    *(__nv_bfloat162*)(Clo + (size_t)r * 512 + cc) = __halves2bfloat162(
                        __float2bfloat16(o0 - __bfloat162float(h0)),
                        __float2bfloat16(o1 - __bfloat162float(h1)));
                } else if (EPI == 1) {
                    const __nv_bfloat162 lh = *(const __nv_bfloat162*)(Chi + (size_t)r * 512 + cc);
                    const __nv_bfloat162 ll = *(const __nv_bfloat162*)(Clo + (size_t)r * 512 + cc);
                    const float lf0 = __low2float(lh)  + __low2float(ll);
                    const float lf1 = __high2float(lh) + __high2float(ll);
                    const float o0 = g * sigf(v0 + bc[cc])     + (1.f - g) * lf0;
                    const float o1 = g * sigf(v1 + bc[cc + 1]) + (1.f - g) * lf1;
                    *(float2*)(C + (size_t)r * ldc + cc) = make_float2(o0, o1);
                } else {
                    *(float2*)(C + (size_t)r * ldc + cc) = make_float2(v0, v1);
                }
            }
        }
    }
}

template <int EPI, int NT, int NS, int THREADS>
__global__ __launch_bounds__(THREADS, 1)
void tgemm_k(const __nv_bfloat16* __restrict__ Ahi, const __nv_bfloat16* __restrict__ Alo,
             const __nv_bfloat16* __restrict__ Bhi, const __nv_bfloat16* __restrict__ Blo,
             float* __restrict__ C, __nv_bfloat16* Chi, __nv_bfloat16* Clo,
             int M, int K, int lda, int ldb, int ldc,
             const float* __restrict__ biasc, const float* __restrict__ attn,
             const float* __restrict__ upd)
{
    extern __shared__ char dsm[];
    gemm_tile<EPI, NT, NS, THREADS>(Ahi, Alo, Bhi, Blo, C, Chi, Clo, M, K, lda, ldb, ldc,
                                    biasc, attn, upd,
                                    blockIdx.x * 128, blockIdx.y * NT, smem_u32(dsm));
}

#define SMEM_128 (3 * (2 * 128 * ROWB + 2 * 128 * ROWB))
#define SMEM_64  (4 * (2 * 128 * ROWB + 2 * 64  * ROWB))

// ---------------------------------------------------------------------------
// grid barrier (148 co-resident CTAs)
// ---------------------------------------------------------------------------
__device__ __forceinline__ void grid_barrier(int nctas) {
    __syncthreads();
    if (threadIdx.x == 0) {
        __threadfence();
        const unsigned gen = *(volatile unsigned*)&g_bar_gen;
        if (atomicAdd(&g_bar_count, 1) == nctas - 1) {
            g_bar_count = 0;
            __threadfence();
            atomicAdd(&g_bar_gen, 1u);
        } else {
            while (*(volatile unsigned*)&g_bar_gen == gen) {}
            __threadfence();
        }
    }
    __syncthreads();
}

// ---------------------------------------------------------------------------
// persistent join kernel: levels 3..8, K-split to fill 148 CTAs
// ---------------------------------------------------------------------------
__global__ __launch_bounds__(256, 1)
void joinp_k(__nv_bfloat16* __restrict__ levhi, __nv_bfloat16* __restrict__ levlo,
             const __nv_bfloat16* __restrict__ Wjhi, const __nv_bfloat16* __restrict__ Wjlo)
{
    extern __shared__ char dsm[];
    const uint32_t sbase = smem_u32(dsm);

#pragma unroll 1
    for (int li = 0; li < 6; li++) {
        const int l    = li + 3;
        const int M    = 64 * (256 >> l);
        const int S    = c_S[li];
        const int Klen = 1024 / S;
        const int nsub = c_Mt[li] * 8 * S;

        const __nv_bfloat16* ahi = levhi + (size_t)c_roff[l - 1] * 512;
        const __nv_bfloat16* alo = levlo + (size_t)c_roff[l - 1] * 512;
        __nv_bfloat16* chi = levhi + (size_t)c_roff[l] * 512;
        __nv_bfloat16* clo = levlo + (size_t)c_roff[l] * 512;

        const int st = blockIdx.x;
        if (st < nsub) {
            const int sp = st % S;
            const int t2 = st / S;
            const int nt = t2 & 7;
            const int mt = t2 >> 3;
            if (S == 1) {
                gemm_tile<0, 64, 4, 256>(ahi, alo, Wjhi, Wjlo, nullptr, chi, clo,
                                         M, 1024, 1024, 1024, 512,
                                         nullptr, nullptr, nullptr,
                                         mt * 128, nt * 64, sbase);
            } else {
                // bias C so absolute-row stores land tile-relative in the slab
                float* Cp = g_part + (size_t)st * 8192 - (size_t)mt * 128 * 64;
                gemm_tile<2, 64, 4, 256>(ahi + sp * Klen, alo + sp * Klen,
                                         Wjhi + (size_t)(nt * 64) * 1024 + sp * Klen,
                                         Wjlo + (size_t)(nt * 64) * 1024 + sp * Klen,
                                         Cp, nullptr, nullptr,
                                         M, Klen, 1024, 1024, 64,
                                         nullptr, nullptr, nullptr,
                                         mt * 128, 0, sbase);
            }
        }
        grid_barrier(gridDim.x);

        if (S > 1) {
            // reduce partials -> relu -> bf16 hi/lo planes
            const int total = M * 512;
            for (int idx = blockIdx.x * 256 + threadIdx.x; idx < total;
                 idx += gridDim.x * 256) {
                const int r  = idx >> 9;
                const int c  = idx & 511;
                const int mt = r >> 7;
                const int nt = c >> 6;
                const size_t base = (size_t)((mt * 8 + nt) * S) * 8192
                                    + (r & 127) * 64 + (c & 63);
                float v = 0.f;
                for (int p = 0; p < S; p++) v += g_part[base + (size_t)p * 8192];
                v = fmaxf(v, 0.f);
                const __nv_bfloat16 h = __float2bfloat16(v);
                chi[(size_t)r * 512 + c] = h;
                clo[(size_t)r * 512 + c] = __float2bfloat16(v - __bfloat162float(h));
            }
            grid_barrier(gridDim.x);
        }
    }
}

// ---------------------------------------------------------------------------
// LSTM z GEMM, K-split x4: grid (4, 32); partial s -> g_z4[s]
// ---------------------------------------------------------------------------
__global__ __launch_bounds__(256, 1)
void lstmgemm_k(const __nv_bfloat16* __restrict__ zAhi, const __nv_bfloat16* __restrict__ zAlo,
                const __nv_bfloat16* __restrict__ Bzhi, const __nv_bfloat16* __restrict__ Bzlo)
{
    extern __shared__ char dsm[];
    const int s  = blockIdx.x;
    const int nt = blockIdx.y;
    gemm_tile<2, 64, 4, 256>(zAhi + s * 256, zAlo + s * 256,
                             Bzhi + s * 256, Bzlo + s * 256,
                             g_z4 + (size_t)s * (BSZ * 2048), nullptr, nullptr,
                             64, 256, 1024, 1024, 2048,
                             nullptr, nullptr, nullptr,
                             0, nt * 64, smem_u32(dsm));
}

// ---------------------------------------------------------------------------
// fused prep kernel: input split + 5 weight splits + ctrl + biasc
// ---------------------------------------------------------------------------
__device__ __forceinline__ void wsplit_body(const float* __restrict__ W,
                                            __nv_bfloat16* __restrict__ H,
                                            __nv_bfloat16* __restrict__ L,
                                            int Nsrc, int ldK, int koff,
                                            int bx, int by, float* shbuf)
{
    float (*t)[33] = (float(*)[33])shbuf;
    const int k0 = bx * 32, n0 = by * 32;
    const int tx = threadIdx.x & 31, ty = threadIdx.x >> 5;
    for (int r = ty; r < 32; r += 8)
        t[r][tx] = W[(size_t)(k0 + r) * Nsrc + n0 + tx];
    __syncthreads();
    for (int r = ty; r < 32; r += 8) {
        const float x = t[tx][r];
        const __nv_bfloat16 h = __float2bfloat16(x);
        H[(size_t)(n0 + r) * ldK + koff + k0 + tx] = h;
        L[(size_t)(n0 + r) * ldK + koff + k0 + tx] = __float2bfloat16(x - __bfloat162float(h));
    }
}

__global__ __launch_bounds__(256)
void prep_k(const float4* __restrict__ inputs4,
            const float* __restrict__ h0,
            const float* __restrict__ W_t, const float* __restrict__ W_j,
            const float* __restrict__ W_s, const float* __restrict__ W_h,
            const float* __restrict__ W_T,
            const float* __restrict__ kern, const float* __restrict__ rec)
{
    __shared__ float shbuf[32 * 33];
    const int blk = blockIdx.x;
    const int tid = threadIdx.x;

    if (blk < 8192) {
        const int i = blk * 256 + tid;
        const float4 v = inputs4[i];
        __nv_bfloat162* H = (__nv_bfloat162*)g_Ahi;
        __nv_bfloat162* L = (__nv_bfloat162*)g_Alo;
        const __nv_bfloat16 hx = __float2bfloat16(v.x);
        const __nv_bfloat16 hy = __float2bfloat16(v.y);
        const __nv_bfloat16 hz = __float2bfloat16(v.z);
        const __nv_bfloat16 hw = __float2bfloat16(v.w);
        H[2 * i]     = __halves2bfloat162(hx, hy);
        H[2 * i + 1] = __halves2bfloat162(hz, hw);
        L[2 * i]     = __halves2bfloat162(__float2bfloat16(v.x - __bfloat162float(hx)),
                                          __float2bfloat16(v.y - __bfloat162float(hy)));
        L[2 * i + 1] = __halves2bfloat162(__float2bfloat16(v.z - __bfloat162float(hz)),
                                          __float2bfloat16(v.w - __bfloat162float(hw)));
    } else if (blk < 8448) {
        const int j = blk - 8192;
        wsplit_body(W_t, g_Wthi, g_Wtlo, 512, 512, 0, j % 16, j / 16, shbuf);
    } else if (blk < 8704) {
        const int j = blk - 8448;
        wsplit_body(W_h, g_Whhi, g_Whlo, 512, 512, 0, j % 16, j / 16, shbuf);
    } else if (blk < 9216) {
        const int j = blk - 8704;
        wsplit_body(W_j, g_Wjhi, g_Wjlo, 512, 1024, 0, j % 32, j / 32, shbuf);
    } else if (blk < 10240) {
        const int j = blk - 9216;
        wsplit_body(kern, g_Bzhi, g_Bzlo, 2048, 1024, 0, j % 16, j / 16, shbuf);
    } else if (blk < 11264) {
        const int j = blk - 10240;
        wsplit_body(rec, g_Bzhi, g_Bzlo, 2048, 1024, 512, j % 16, j / 16, shbuf);
    } else if (blk < 11328) {
        const int b = blk - 11264;
        const int lane = tid & 31;
        const int w = tid >> 5;
        if (w < 2) {
            const float* wv = (w == 0 ? W_s : W_T) + 512;
            const float* hr = h0 + b * 512;
            float s = 0.f;
#pragma unroll
            for (int i = 0; i < 16; i++) s = fmaf(hr[lane + i * 32], wv[lane + i * 32], s);
#pragma unroll
            for (int o = 16; o; o >>= 1) s += __shfl_xor_sync(0xffffffffu, s, o);
            if (lane == 0) { if (w == 0) g_sctrl[b] = s; else g_tctrl[b] = s; }
        }
    } else {
        const int b = blk - 11328;
        float* sh = shbuf;
        sh[tid]       = h0[b * 512 + tid];
        sh[tid + 256] = h0[b * 512 + tid + 256];
        __syncthreads();
        const float* wp = W_h + (size_t)512 * 512 + tid;
        float a0 = 0.f, a1 = 0.f;
#pragma unroll 16
        for (int u = 0; u < 512; u++) {
            const float hv = sh[u];
            a0 = fmaf(hv, wp[(size_t)u * 512], a0);
            a1 = fmaf(hv, wp[(size_t)u * 512 + 256], a1);
        }
        g_biasc[b * 512 + tid]       = a0;
        g_biasc[b * 512 + tid + 256] = a1;
    }
}

// ---------------------------------------------------------------------------
// fused mr + upd
// ---------------------------------------------------------------------------
__global__ __launch_bounds__(256)
void mrupd_k(const float* __restrict__ Ws, const float* __restrict__ WT)
{
    const int gw   = blockIdx.x * 8 + (threadIdx.x >> 5);
    const int lane = threadIdx.x & 31;

    const __nv_bfloat162* hi;
    const __nv_bfloat162* lo;
    const float2* wv;
    if (gw < 16384) {
        hi = (const __nv_bfloat162*)(g_leafhi + (size_t)gw * 512);
        lo = (const __nv_bfloat162*)(g_leaflo + (size_t)gw * 512);
        wv = (const float2*)WT;
    } else {
        const int node = gw - 16384;
        if (node >= 16320) return;
        hi = (const __nv_bfloat162*)(g_levhi + (size_t)node * 512);
        lo = (const __nv_bfloat162*)(g_levlo + (size_t)node * 512);
        wv = (const float2*)Ws;
    }
    float s = 0.f;
#pragma unroll
    for (int i = 0; i < 8; i++) {
        const int idx = lane + i * 32;
        const __nv_bfloat162 h2 = hi[idx];
        const __nv_bfloat162 l2 = lo[idx];
        const float2 w = wv[idx];
        s = fmaf(__low2float(h2)  + __low2float(l2),  w.x, s);
        s = fmaf(__high2float(h2) + __high2float(l2), w.y, s);
    }
#pragma unroll
    for (int o = 16; o; o >>= 1) s += __shfl_xor_sync(0xffffffffu, s, o);
    if (lane == 0) {
        if (gw < 16384) {
            g_upd[gw] = sigf(s + g_tctrl[gw >> 8]);
        } else {
            const int node = gw - 16384;
            int l = 1;
#pragma unroll
            for (int t = 2; t <= 8; t++)
                if (node >= c_roff[t]) l = t;
            const int m = 256 >> l;
            const int b = (node - c_roff[l]) / m;
            g_mr[node] = sigf(s + g_sctrl[b]);
        }
    }
}

__global__ void attn_k()
{
    __shared__ float sa[2][256];
    const int b = blockIdx.x, t = threadIdx.x;   // 128 threads
    if (t == 0) sa[0][0] = 1.f;
    __syncthreads();
    int cur = 0;
    for (int l = 8; l >= 1; --l) {
        const int m = 256 >> l;
        if (t < m) {
            const float a  = sa[cur][t];
            const float mv = g_mr[c_roff[l] + b * m + t];
            sa[cur ^ 1][2 * t]     = a * (1.f - mv);
            sa[cur ^ 1][2 * t + 1] = a * mv;
        }
        __syncthreads();
        cur ^= 1;
    }
    g_attn[b * 256 + t]       = sa[cur][t];
    g_attn[b * 256 + 128 + t] = sa[cur][128 + t];
}

// fused treeout + LSTM A-plane prep
__global__ __launch_bounds__(512) void treeoutz_k(const float* __restrict__ inputs,
                                                  const float* __restrict__ h0)
{
    __shared__ float sat[256];
    const int b = blockIdx.x, t = threadIdx.x;
    if (t < 256) sat[t] = g_attn[b * 256 + t];
    __syncthreads();
    float a0 = 0.f, a1 = 0.f, a2 = 0.f, a3 = 0.f;
    const float* ip = inputs + (size_t)b * 256 * 512 + t;
#pragma unroll 4
    for (int n = 0; n < 256; n += 4) {
        a0 = fmaf(sat[n],     ip[(size_t)n * 512],       a0);
        a1 = fmaf(sat[n + 1], ip[(size_t)(n + 1) * 512], a1);
        a2 = fmaf(sat[n + 2], ip[(size_t)(n + 2) * 512], a2);
        a3 = fmaf(sat[n + 3], ip[(size_t)(n + 3) * 512], a3);
    }
    const float acc = (a0 + a1) + (a2 + a3);
    const __nv_bfloat16 th = __float2bfloat16(acc);
    g_zAhi[b * 1024 + t] = th;
    g_zAlo[b * 1024 + t] = __float2bfloat16(acc - __bfloat162float(th));
    const float hv = h0[b * 512 + t];
    const __nv_bfloat16 hh = __float2bfloat16(hv);
    g_zAhi[b * 1024 + 512 + t] = hh;
    g_zAlo[b * 1024 + 512 + t] = __float2bfloat16(hv - __bfloat162float(hh));
}

__global__ __launch_bounds__(512) void gate_k(
    const float* __restrict__ c0, const float* __restrict__ bias,
    float* __restrict__ hout, float* __restrict__ cout)
{
    const int b = blockIdx.x, u = threadIdx.x;
    const size_t zo0 = (size_t)b * 2048;
    const float zi = g_z4[zo0 + u]        + g_z4[131072 + zo0 + u]
                   + g_z4[262144 + zo0 + u] + g_z4[393216 + zo0 + u] + bias[u];
    const float zf = g_z4[zo0 + 512 + u]  + g_z4[131072 + zo0 + 512 + u]
                   + g_z4[262144 + zo0 + 512 + u] + g_z4[393216 + zo0 + 512 + u] + bias[512 + u];
    const float zg = g_z4[zo0 + 1024 + u] + g_z4[131072 + zo0 + 1024 + u]
                   + g_z4[262144 + zo0 + 1024 + u] + g_z4[393216 + zo0 + 1024 + u] + bias[1024 + u];
    const float zo = g_z4[zo0 + 1536 + u] + g_z4[131072 + zo0 + 1536 + u]
                   + g_z4[262144 + zo0 + 1536 + u] + g_z4[393216 + zo0 + 1536 + u] + bias[1536 + u];
    const float cn = sigf(zf) * c0[b * 512 + u] + sigf(zi) * tanhf(zg);
    hout[b * 512 + u] = sigf(zo) * tanhf(cn);
    cout[b * 512 + u] = cn;
}

// ---------------------------------------------------------------------------
extern "C" void kernel_launch(void* const* d_in, const int* in_sizes, int n_in,
                              void* d_out, int out_size)
{
    const float* inputs = (const float*)d_in[0];
    const float* h0     = (const float*)d_in[1];
    const float* c0     = (const float*)d_in[2];
    const float* W_t    = (const float*)d_in[3];
    const float* W_j    = (const float*)d_in[4];
    const float* W_s    = (const float*)d_in[5];
    const float* W_h    = (const float*)d_in[6];
    const float* W_T    = (const float*)d_in[7];
    const float* kern   = (const float*)d_in[8];
    const float* rec    = (const float*)d_in[9];
    const float* bias   = (const float*)d_in[10];

    float* out      = (float*)d_out;
    float* h_new    = out;
    float* c_new    = out + BSZ * UD;
    float* leaf_new = out + 2 * BSZ * UD;

    float *p_biasc, *p_attn, *p_upd;
    __nv_bfloat16 *p_Ahi, *p_Alo, *p_leafhi, *p_leaflo, *p_levhi, *p_levlo;
    __nv_bfloat16 *p_Wthi, *p_Wtlo, *p_Wjhi, *p_Wjlo, *p_Whhi, *p_Whlo;
    __nv_bfloat16 *p_Bzhi, *p_Bzlo, *p_zAhi, *p_zAlo;
    cudaGetSymbolAddress((void**)&p_biasc,  g_biasc);
    cudaGetSymbolAddress((void**)&p_attn,   g_attn);
    cudaGetSymbolAddress((void**)&p_upd,    g_upd);
    cudaGetSymbolAddress((void**)&p_Ahi,    g_Ahi);
    cudaGetSymbolAddress((void**)&p_Alo,    g_Alo);
    cudaGetSymbolAddress((void**)&p_leafhi, g_leafhi);
    cudaGetSymbolAddress((void**)&p_leaflo, g_leaflo);
    cudaGetSymbolAddress((void**)&p_levhi,  g_levhi);
    cudaGetSymbolAddress((void**)&p_levlo,  g_levlo);
    cudaGetSymbolAddress((void**)&p_Wthi,   g_Wthi);
    cudaGetSymbolAddress((void**)&p_Wtlo,   g_Wtlo);
    cudaGetSymbolAddress((void**)&p_Wjhi,   g_Wjhi);
    cudaGetSymbolAddress((void**)&p_Wjlo,   g_Wjlo);
    cudaGetSymbolAddress((void**)&p_Whhi,   g_Whhi);
    cudaGetSymbolAddress((void**)&p_Whlo,   g_Whlo);
    cudaGetSymbolAddress((void**)&p_Bzhi,   g_Bzhi);
    cudaGetSymbolAddress((void**)&p_Bzlo,   g_Bzlo);
    cudaGetSymbolAddress((void**)&p_zAhi,   g_zAhi);
    cudaGetSymbolAddress((void**)&p_zAlo,   g_zAlo);

    cudaFuncSetAttribute((const void*)tgemm_k<0, 64, 4, 256>,
                         cudaFuncAttributeMaxDynamicSharedMemorySize, SMEM_64);
    cudaFuncSetAttribute((const void*)tgemm_k<1, 64, 4, 256>,
                         cudaFuncAttributeMaxDynamicSharedMemorySize, SMEM_64);
    cudaFuncSetAttribute((const void*)tgemm_k<0, 128, 3, 256>,
                         cudaFuncAttributeMaxDynamicSharedMemorySize, SMEM_128);
    cudaFuncSetAttribute((const void*)joinp_k,
                         cudaFuncAttributeMaxDynamicSharedMemorySize, SMEM_64);
    cudaFuncSetAttribute((const void*)lstmgemm_k,
                         cudaFuncAttributeMaxDynamicSharedMemorySize, SMEM_64);

    // 1: all conversions + ctrl + biasc
    prep_k<<<11392, 256>>>((const float4*)inputs, h0, W_t, W_j, W_s, W_h, W_T, kern, rec);

    // 2: leaf embed (NT=64 fine tiles: 1024 CTAs, ~7 even waves)
    tgemm_k<0, 64, 4, 256><<<dim3(128, 8), 256, SMEM_64>>>(
        p_Ahi, p_Alo, p_Wthi, p_Wtlo, nullptr, p_leafhi, p_leaflo,
        16384, 512, 512, 512, 512, nullptr, nullptr, nullptr);

    // 3-4: join levels 1-2 (wave-aligned at NT=128)
    tgemm_k<0, 128, 3, 256><<<dim3(64, 4), 256, SMEM_128>>>(
        p_leafhi, p_leaflo, p_Wjhi, p_Wjlo, nullptr,
        p_levhi + (size_t)h_roff[1] * 512, p_levlo + (size_t)h_roff[1] * 512,
        8192, 1024, 1024, 1024, 512, nullptr, nullptr, nullptr);
    tgemm_k<0, 128, 3, 256><<<dim3(32, 4), 256, SMEM_128>>>(
        p_levhi + (size_t)h_roff[1] * 512, p_levlo + (size_t)h_roff[1] * 512,
        p_Wjhi, p_Wjlo, nullptr,
        p_levhi + (size_t)h_roff[2] * 512, p_levlo + (size_t)h_roff[2] * 512,
        4096, 1024, 1024, 1024, 512, nullptr, nullptr, nullptr);

    // 5: join levels 3-8, persistent K-split
    joinp_k<<<148, 256, SMEM_64>>>(p_levhi, p_levlo, p_Wjhi, p_Wjlo);

    // 6: mr + upd fused
    mrupd_k<<<4088, 256>>>(W_s, W_T);

    // 7: attention walk
    attn_k<<<64, 128>>>();

    // 8: tree_out + LSTM A planes
    treeoutz_k<<<64, 512>>>(inputs, h0);

    // 9: cand GEMM -> leaf_new (NT=64 fine tiles)
    tgemm_k<1, 64, 4, 256><<<dim3(128, 8), 256, SMEM_64>>>(
        p_leafhi, p_leaflo, p_Whhi, p_Whlo, leaf_new, p_leafhi, p_leaflo,
        16384, 512, 512, 512, 512, p_biasc, p_attn, p_upd);

    // 10: LSTM z GEMM, K-split x4
    lstmgemm_k<<<dim3(4, 32), 256, SMEM_64>>>(p_zAhi, p_zAlo, p_Bzhi, p_Bzlo);

    // 11: gates
    gate_k<<<64, 512>>>(c0, bias, h_new, c_new);
}

// round 15
// speedup vs baseline: 2.0482x; 1.1339x over previous
#include <cuda_runtime.h>
#include <cuda_bf16.h>
#include <cstdint>
#include <math.h>

#define BSZ   64
#define NLEAF 256
#define ED    512
#define DD    512
#define UD    512

// ---------------------------------------------------------------------------
// scratch (device globals; no allocation allowed)
// ---------------------------------------------------------------------------
__device__ __nv_bfloat16 g_Ahi   [BSZ * NLEAF * ED];
__device__ __nv_bfloat16 g_Alo   [BSZ * NLEAF * ED];
__device__ __nv_bfloat16 g_leafhi[BSZ * NLEAF * DD];
__device__ __nv_bfloat16 g_leaflo[BSZ * NLEAF * DD];
__device__ __nv_bfloat16 g_levhi [BSZ * 255  * DD];
__device__ __nv_bfloat16 g_levlo [BSZ * 255  * DD];
__device__ __nv_bfloat16 g_Wthi[512 * 512],  g_Wtlo[512 * 512];   // [n][k]
__device__ __nv_bfloat16 g_Wjhi[512 * 1024], g_Wjlo[512 * 1024];  // [n][k]
__device__ __nv_bfloat16 g_Whhi[512 * 512],  g_Whlo[512 * 512];   // [n][k]
__device__ __nv_bfloat16 g_Bzhi[2048 * 1024], g_Bzlo[2048 * 1024];// [n][k] (kern;rec)
__device__ __nv_bfloat16 g_zAhi[BSZ * 1024],  g_zAlo[BSZ * 1024]; // [tree|h0]
__device__ float g_z4    [4 * BSZ * 2048];     // LSTM K-split partials
__device__ float g_part  [128 * 128 * 64];     // join K-split partials (4MB)
__device__ float g_mr    [BSZ * 255];
__device__ float g_attn  [BSZ * NLEAF];
__device__ float g_sctrl [BSZ];
__device__ float g_tctrl [BSZ];
__device__ float g_biasc [BSZ * DD];
__device__ float g_upd   [BSZ * NLEAF];
__device__ int      g_bar_count;
__device__ unsigned g_bar_gen;

__constant__ int c_roff[9] = {0, 0, 8192, 12288, 14336, 15360, 15872, 16128, 16256};
__constant__ int c_Mt[6] = {16, 8, 4, 2, 1, 1};   // M-tiles per level 3..8
__constant__ int c_S [6] = {1,  2, 4, 8, 8, 8};   // K-splits per level 3..8
static const int h_roff[9] = {0, 0, 8192, 12288, 14336, 15360, 15872, 16128, 16256};

__device__ __forceinline__ float sigf(float x) { return 1.f / (1.f + __expf(-x)); }

__device__ __forceinline__ uint32_t smem_u32(const void* p) {
    uint32_t a;
    asm("{ .reg .u64 t; cvta.to.shared.u64 t, %1; cvt.u32.u64 %0, t; }" : "=r"(a) : "l"(p));
    return a;
}

__device__ __forceinline__ void cp_async16(uint32_t dst, const void* src) {
    asm volatile("cp.async.cg.shared.global [%0], [%1], 16;" :: "r"(dst), "l"(src));
}
__device__ __forceinline__ void cp_commit() {
    asm volatile("cp.async.commit_group;" ::: "memory");
}
template <int N>
__device__ __forceinline__ void cp_wait() {
    asm volatile("cp.async.wait_group %0;" :: "n"(N) : "memory");
}

__device__ __forceinline__ void ldsm_x4(uint32_t (&r)[4], uint32_t addr) {
    asm volatile("ldmatrix.sync.aligned.m8n8.x4.shared.b16 {%0,%1,%2,%3}, [%4];"
                 : "=r"(r[0]), "=r"(r[1]), "=r"(r[2]), "=r"(r[3]) : "r"(addr));
}

__device__ __forceinline__ void mma16816(float (&d)[4], const uint32_t (&a)[4],
                                         uint32_t b0, uint32_t b1) {
    asm volatile(
        "mma.sync.aligned.m16n8k16.row.col.f32.bf16.bf16.f32 "
        "{%0,%1,%2,%3},{%4,%5,%6,%7},{%8,%9},{%0,%1,%2,%3};"
        : "+f"(d[0]), "+f"(d[1]), "+f"(d[2]), "+f"(d[3])
        : "r"(a[0]), "r"(a[1]), "r"(a[2]), "r"(a[3]), "r"(b0), "r"(b1));
}

// ---------------------------------------------------------------------------
// GEMM tile body: one 128 x NT tile of C = A @ B (3-product fp32 emulation).
// ---------------------------------------------------------------------------
#define ROWB 144

template <int EPI, int NT, int NS, int THREADS>
__device__ __forceinline__ void gemm_tile(
    const __nv_bfloat16* __restrict__ Ahi, const __nv_bfloat16* __restrict__ Alo,
    const __nv_bfloat16* __restrict__ Bhi, const __nv_bfloat16* __restrict__ Blo,
    float* __restrict__ C, __nv_bfloat16* Chi, __nv_bfloat16* Clo,
    int M, int K, int lda, int ldb, int ldc,
    const float* __restrict__ biasc, const float* __restrict__ attn,
    const float* __restrict__ upd,
    int row0, int col0, uint32_t sbase)
{
    constexpr int PLANE_A = 128 * ROWB;
    constexpr int PLANE_B = NT * ROWB;
    constexpr int STAGE_B = 2 * PLANE_A + 2 * PLANE_B;
    constexpr int NWARPS  = THREADS / 32;
    constexpr int NWN     = NT / 32;
    constexpr int NWM     = NWARPS / NWN;
    constexpr int MF      = 128 / (16 * NWM);
    static_assert(NWM * NWN == NWARPS && MF >= 1, "bad layout");

    const int tid  = threadIdx.x;
    const int lane = tid & 31;
    const int wid  = tid >> 5;
    const int wm   = wid % NWM;
    const int wn   = wid / NWM;

    const __nv_bfloat16* srcs[4] = {Ahi, Alo, Bhi, Blo};

    const int laneRowA = (lane & 7) + ((lane >> 3) & 1) * 8;
    const int laneKA   = ((lane >> 4) & 1) * 8;
    const int laneRowB = (lane & 7) + ((lane >> 4) & 1) * 8;
    const int laneKB   = ((lane >> 3) & 1) * 8;

    float acc[MF][4][4];
#pragma unroll
    for (int i = 0; i < MF; i++)
#pragma unroll
        for (int j = 0; j < 4; j++)
#pragma unroll
            for (int v = 0; v < 4; v++) acc[i][j][v] = 0.f;

    const int NC = K >> 6;

    auto load_stage = [&](int c) {
        const int k0 = c << 6;
        const uint32_t sb = sbase + (uint32_t)(c % NS) * STAGE_B;
#pragma unroll
        for (int t = 0; t < 4; t++) {
            const __nv_bfloat16* S = srcs[t];
            const int ld    = (t < 2) ? lda : ldb;
            const int iters = ((t < 2 ? 128 : NT) * 8) / THREADS;
            const uint32_t poff = (t == 0) ? 0u : (t == 1) ? (uint32_t)PLANE_A
                                : (t == 2) ? (uint32_t)(2 * PLANE_A)
                                : (uint32_t)(2 * PLANE_A + PLANE_B);
#pragma unroll
            for (int j = 0; j < 4; j++) {
                if (j >= iters) break;
                const int idx = j * THREADS + tid;
                const int row = idx >> 3;
                const int c16 = idx & 7;
                const int gr  = (t < 2) ? min(row0 + row, M - 1) : (col0 + row);
                const void* src = S + (size_t)gr * ld + k0 + c16 * 8;
                cp_async16(sb + poff + row * ROWB + c16 * 16, src);
            }
        }
        cp_commit();
    };

#pragma unroll
    for (int s = 0; s < NS - 1; s++) {
        if (s < NC) load_stage(s); else cp_commit();
    }

    for (int c = 0; c < NC; c++) {
        cp_wait<NS - 2>();
        __syncthreads();
        if (c + NS - 1 < NC) load_stage(c + NS - 1); else cp_commit();

        const uint32_t sb = sbase + (uint32_t)(c % NS) * STAGE_B;
        const uint32_t aH = sb;
        const uint32_t aL = sb + PLANE_A;
        const uint32_t bH = sb + 2 * PLANE_A;
        const uint32_t bL = sb + 2 * PLANE_A + PLANE_B;

#pragma unroll
        for (int ks = 0; ks < 4; ks++) {
            uint32_t ah[MF][4], al[MF][4];
#pragma unroll
            for (int mf = 0; mf < MF; mf++) {
                const uint32_t off = (uint32_t)((wm * (MF * 16) + mf * 16 + laneRowA) * ROWB
                                                + (ks * 16 + laneKA) * 2);
                ldsm_x4(ah[mf], aH + off);
                ldsm_x4(al[mf], aL + off);
            }
            uint32_t bh[4][2], bl[4][2];
#pragma unroll
            for (int np = 0; np < 2; np++) {
                const uint32_t off = (uint32_t)((wn * 32 + np * 16 + laneRowB) * ROWB
                                                + (ks * 16 + laneKB) * 2);
                uint32_t th[4], tl[4];
                ldsm_x4(th, bH + off);
                ldsm_x4(tl, bL + off);
                bh[2 * np][0] = th[0]; bh[2 * np][1] = th[1];
                bh[2 * np + 1][0] = th[2]; bh[2 * np + 1][1] = th[3];
                bl[2 * np][0] = tl[0]; bl[2 * np][1] = tl[1];
                bl[2 * np + 1][0] = tl[2]; bl[2 * np + 1][1] = tl[3];
            }
#pragma unroll
            for (int mf = 0; mf < MF; mf++)
#pragma unroll
                for (int nf = 0; nf < 4; nf++) {
                    mma16816(acc[mf][nf], ah[mf], bh[nf][0], bh[nf][1]);
                    mma16816(acc[mf][nf], ah[mf], bl[nf][0], bl[nf][1]);
                    mma16816(acc[mf][nf], al[mf], bh[nf][0], bh[nf][1]);
                }
        }
    }
    __syncthreads();

#pragma unroll
    for (int mf = 0; mf < MF; mf++) {
#pragma unroll
        for (int half = 0; half < 2; half++) {
            const int r = row0 + wm * (MF * 16) + mf * 16 + (lane >> 2) + half * 8;
            if (r >= M) continue;
            float g = 0.f;
            const float* bc = nullptr;
            if (EPI == 1) {
                g  = attn[r] * upd[r];
                bc = biasc + (size_t)(r >> 8) * 512;
            }
#pragma unroll
            for (int nf = 0; nf < 4; nf++) {
                const int cc = col0 + wn * 32 + nf * 8 + (lane & 3) * 2;
                const float v0 = acc[mf][nf][half * 2 + 0];
                const float v1 = acc[mf][nf][half * 2 + 1];
                if (EPI == 0) {
                    const float o0 = fmaxf(v0, 0.f);
                    const float o1 = fmaxf(v1, 0.f);
                    const __nv_bfloat16 h0 = __float2bfloat16(o0);
                    const __nv_bfloat16 h1 = __float2bfloat16(o1);
                    *(__nv_bfloat162*)(Chi + (size_t)r * 512 + cc) = __halves2bfloat162(h0, h1);
                    *(__nv_bfloat162*)(Clo + (size_t)r * 512 + cc) = __halves2bfloat162(
                        __float2bfloat16(o0 - __bfloat162float(h0)),
                        __float2bfloat16(o1 - __bfloat162float(h1)));
                } else if (EPI == 1) {
                    const __nv_bfloat162 lh = *(const __nv_bfloat162*)(Chi + (size_t)r * 512 + cc);
                    const __nv_bfloat162 ll = *(const __nv_bfloat162*)(Clo + (size_t)r * 512 + cc);
                    const float lf0 = __low2float(lh)  + __low2float(ll);
                    const float lf1 = __high2float(lh) + __high2float(ll);
                    const float o0 = g * sigf(v0 + bc[cc])     + (1.f - g) * lf0;
                    const float o1 = g * sigf(v1 + bc[cc + 1]) + (1.f - g) * lf1;
                    *(float2*)(C + (size_t)r * ldc + cc) = make_float2(o0, o1);
                } else {
                    *(float2*)(C + (size_t)r * ldc + cc) = make_float2(v0, v1);
                }
            }
        }
    }
}

template <int EPI, int NT, int NS, int THREADS>
__global__ __launch_bounds__(THREADS, 1)
void tgemm_k(const __nv_bfloat16* __restrict__ Ahi, const __nv_bfloat16* __restrict__ Alo,
             const __nv_bfloat16* __restrict__ Bhi, const __nv_bfloat16* __restrict__ Blo,
             float* __restrict__ C, __nv_bfloat16* Chi, __nv_bfloat16* Clo,
             int M, int K, int lda, int ldb, int ldc,
             const float* __restrict__ biasc, const float* __restrict__ attn,
             const float* __restrict__ upd)
{
    extern __shared__ char dsm[];
    gemm_tile<EPI, NT, NS, THREADS>(Ahi, Alo, Bhi, Blo, C, Chi, Clo, M, K, lda, ldb, ldc,
                                    biasc, attn, upd,
                                    blockIdx.x * 128, blockIdx.y * NT, smem_u32(dsm));
}

#define SMEM_128 (3 * (2 * 128 * ROWB + 2 * 128 * ROWB))
#define SMEM_64  (4 * (2 * 128 * ROWB + 2 * 64  * ROWB))

// ---------------------------------------------------------------------------
// grid barrier
// ---------------------------------------------------------------------------
__device__ __forceinline__ void grid_barrier(int nctas) {
    __syncthreads();
    if (threadIdx.x == 0) {
        __threadfence();
        const unsigned gen = *(volatile unsigned*)&g_bar_gen;
        if (atomicAdd(&g_bar_count, 1) == nctas - 1) {
            g_bar_count = 0;
            __threadfence();
            atomicAdd(&g_bar_gen, 1u);
        } else {
            while (*(volatile unsigned*)&g_bar_gen == gen) {}
            __threadfence();
        }
    }
    __syncthreads();
}

// ---------------------------------------------------------------------------
// persistent join kernel: levels 3..8, K-split
// ---------------------------------------------------------------------------
__global__ __launch_bounds__(256, 1)
void joinp_k(__nv_bfloat16* __restrict__ levhi, __nv_bfloat16* __restrict__ levlo,
             const __nv_bfloat16* __restrict__ Wjhi, const __nv_bfloat16* __restrict__ Wjlo)
{
    extern __shared__ char dsm[];
    const uint32_t sbase = smem_u32(dsm);

#pragma unroll 1
    for (int li = 0; li < 6; li++) {
        const int l    = li + 3;
        const int M    = 64 * (256 >> l);
        const int S    = c_S[li];
        const int Klen = 1024 / S;
        const int nsub = c_Mt[li] * 8 * S;

        const __nv_bfloat16* ahi = levhi + (size_t)c_roff[l - 1] * 512;
        const __nv_bfloat16* alo = levlo + (size_t)c_roff[l - 1] * 512;
        __nv_bfloat16* chi = levhi + (size_t)c_roff[l] * 512;
        __nv_bfloat16* clo = levlo + (size_t)c_roff[l] * 512;

        const int st = blockIdx.x;
        if (st < nsub) {
            const int sp = st % S;
            const int t2 = st / S;
            const int nt = t2 & 7;
            const int mt = t2 >> 3;
            if (S == 1) {
                gemm_tile<0, 64, 4, 256>(ahi, alo, Wjhi, Wjlo, nullptr, chi, clo,
                                         M, 1024, 1024, 1024, 512,
                                         nullptr, nullptr, nullptr,
                                         mt * 128, nt * 64, sbase);
            } else {
                float* Cp = g_part + (size_t)st * 8192 - (size_t)mt * 128 * 64;
                gemm_tile<2, 64, 4, 256>(ahi + sp * Klen, alo + sp * Klen,
                                         Wjhi + (size_t)(nt * 64) * 1024 + sp * Klen,
                                         Wjlo + (size_t)(nt * 64) * 1024 + sp * Klen,
                                         Cp, nullptr, nullptr,
                                         M, Klen, 1024, 1024, 64,
                                         nullptr, nullptr, nullptr,
                                         mt * 128, 0, sbase);
            }
        }
        grid_barrier(gridDim.x);

        if (S > 1) {
            const int total = M * 512;
            for (int idx = blockIdx.x * 256 + threadIdx.x; idx < total;
                 idx += gridDim.x * 256) {
                const int r  = idx >> 9;
                const int c  = idx & 511;
                const int mt = r >> 7;
                const int nt = c >> 6;
                const size_t base = (size_t)((mt * 8 + nt) * S) * 8192
                                    + (r & 127) * 64 + (c & 63);
                float v = 0.f;
                for (int p = 0; p < S; p++) v += g_part[base + (size_t)p * 8192];
                v = fmaxf(v, 0.f);
                const __nv_bfloat16 h = __float2bfloat16(v);
                chi[(size_t)r * 512 + c] = h;
                clo[(size_t)r * 512 + c] = __float2bfloat16(v - __bfloat162float(h));
            }
            grid_barrier(gridDim.x);
        }
    }
}

// ---------------------------------------------------------------------------
// LSTM z GEMM, K-split x4
// ---------------------------------------------------------------------------
__global__ __launch_bounds__(256, 1)
void lstmgemm_k(const __nv_bfloat16* __restrict__ zAhi, const __nv_bfloat16* __restrict__ zAlo,
                const __nv_bfloat16* __restrict__ Bzhi, const __nv_bfloat16* __restrict__ Bzlo)
{
    extern __shared__ char dsm[];
    const int s  = blockIdx.x;
    const int nt = blockIdx.y;
    gemm_tile<2, 64, 4, 256>(zAhi + s * 256, zAlo + s * 256,
                             Bzhi + s * 256, Bzlo + s * 256,
                             g_z4 + (size_t)s * (BSZ * 2048), nullptr, nullptr,
                             64, 256, 1024, 1024, 2048,
                             nullptr, nullptr, nullptr,
                             0, nt * 64, smem_u32(dsm));
}

// ---------------------------------------------------------------------------
// prep kernels
// ---------------------------------------------------------------------------
__device__ __forceinline__ void wsplit_body(const float* __restrict__ W,
                                            __nv_bfloat16* __restrict__ H,
                                            __nv_bfloat16* __restrict__ L,
                                            int Nsrc, int ldK, int koff,
                                            int bx, int by, float* shbuf)
{
    float (*t)[33] = (float(*)[33])shbuf;
    const int k0 = bx * 32, n0 = by * 32;
    const int tx = threadIdx.x & 31, ty = threadIdx.x >> 5;
    for (int r = ty; r < 32; r += 8)
        t[r][tx] = W[(size_t)(k0 + r) * Nsrc + n0 + tx];
    __syncthreads();
    for (int r = ty; r < 32; r += 8) {
        const float x = t[tx][r];
        const __nv_bfloat16 h = __float2bfloat16(x);
        H[(size_t)(n0 + r) * ldK + koff + k0 + tx] = h;
        L[(size_t)(n0 + r) * ldK + koff + k0 + tx] = __float2bfloat16(x - __bfloat162float(h));
    }
}

// prep_a: input split + W_t split  (8448 blocks) — gates the leaf GEMM
__global__ __launch_bounds__(256)
void prepa_k(const float4* __restrict__ inputs4, const float* __restrict__ W_t)
{
    __shared__ float shbuf[32 * 33];
    const int blk = blockIdx.x;
    const int tid = threadIdx.x;

    if (blk < 8192) {
        const int i = blk * 256 + tid;
        const float4 v = inputs4[i];
        __nv_bfloat162* H = (__nv_bfloat162*)g_Ahi;
        __nv_bfloat162* L = (__nv_bfloat162*)g_Alo;
        const __nv_bfloat16 hx = __float2bfloat16(v.x);
        const __nv_bfloat16 hy = __float2bfloat16(v.y);
        const __nv_bfloat16 hz = __float2bfloat16(v.z);
        const __nv_bfloat16 hw = __float2bfloat16(v.w);
        H[2 * i]     = __halves2bfloat162(hx, hy);
        H[2 * i + 1] = __halves2bfloat162(hz, hw);
        L[2 * i]     = __halves2bfloat162(__float2bfloat16(v.x - __bfloat162float(hx)),
                                          __float2bfloat16(v.y - __bfloat162float(hy)));
        L[2 * i + 1] = __halves2bfloat162(__float2bfloat16(v.z - __bfloat162float(hz)),
                                          __float2bfloat16(v.w - __bfloat162float(hw)));
    } else {
        const int j = blk - 8192;
        wsplit_body(W_t, g_Wthi, g_Wtlo, 512, 512, 0, j % 16, j / 16, shbuf);
    }
}

// prep_b: W_h + W_j + kern + rec splits + ctrl + biasc  (2944 blocks)
__global__ __launch_bounds__(256)
void prepb_k(const float* __restrict__ h0,
             const float* __restrict__ W_j, const float* __restrict__ W_s,
             const float* __restrict__ W_h, const float* __restrict__ W_T,
             const float* __restrict__ kern, const float* __restrict__ rec)
{
    __shared__ float shbuf[32 * 33];
    const int blk = blockIdx.x;
    const int tid = threadIdx.x;
    const int lane = tid & 31;
    const int w = tid >> 5;

    if (blk < 256) {
        wsplit_body(W_h, g_Whhi, g_Whlo, 512, 512, 0, blk % 16, blk / 16, shbuf);
    } else if (blk < 768) {
        const int j = blk - 256;
        wsplit_body(W_j, g_Wjhi, g_Wjlo, 512, 1024, 0, j % 32, j / 32, shbuf);
    } else if (blk < 1792) {
        const int j = blk - 768;
        wsplit_body(kern, g_Bzhi, g_Bzlo, 2048, 1024, 0, j % 16, j / 16, shbuf);
    } else if (blk < 2816) {
        const int j = blk - 1792;
        wsplit_body(rec, g_Bzhi, g_Bzlo, 2048, 1024, 512, j % 16, j / 16, shbuf);
    } else if (blk < 2880) {
        const int b = blk - 2816;
        if (w < 2) {
            const float* wv = (w == 0 ? W_s : W_T) + 512;
            const float* hr = h0 + b * 512;
            float s = 0.f;
#pragma unroll
            for (int i = 0; i < 16; i++) s = fmaf(hr[lane + i * 32], wv[lane + i * 32], s);
#pragma unroll
            for (int o = 16; o; o >>= 1) s += __shfl_xor_sync(0xffffffffu, s, o);
            if (lane == 0) { if (w == 0) g_sctrl[b] = s; else g_tctrl[b] = s; }
        }
    } else {
        const int b = blk - 2880;
        float* sh = shbuf;
        sh[tid]       = h0[b * 512 + tid];
        sh[tid + 256] = h0[b * 512 + tid + 256];
        __syncthreads();
        const float* wp = W_h + (size_t)512 * 512 + tid;
        float a0 = 0.f, a1 = 0.f;
#pragma unroll 16
        for (int u = 0; u < 512; u++) {
            const float hv = sh[u];
            a0 = fmaf(hv, wp[(size_t)u * 512], a0);
            a1 = fmaf(hv, wp[(size_t)u * 512 + 256], a1);
        }
        g_biasc[b * 512 + tid]       = a0;
        g_biasc[b * 512 + tid + 256] = a1;
    }
}

// ---------------------------------------------------------------------------
// upd (leaf-based), mr (node-based)
// ---------------------------------------------------------------------------
__global__ __launch_bounds__(256)
void upd_k(const float* __restrict__ WT)
{
    const int gw   = blockIdx.x * 8 + (threadIdx.x >> 5);
    const int lane = threadIdx.x & 31;
    if (gw >= 16384) return;
    const __nv_bfloat162* hi = (const __nv_bfloat162*)(g_leafhi + (size_t)gw * 512);
    const __nv_bfloat162* lo = (const __nv_bfloat162*)(g_leaflo + (size_t)gw * 512);
    const float2* wv = (const float2*)WT;
    float s = 0.f;
#pragma unroll
    for (int i = 0; i < 8; i++) {
        const int idx = lane + i * 32;
        const __nv_bfloat162 h2 = hi[idx];
        const __nv_bfloat162 l2 = lo[idx];
        const float2 w = wv[idx];
        s = fmaf(__low2float(h2)  + __low2float(l2),  w.x, s);
        s = fmaf(__high2float(h2) + __high2float(l2), w.y, s);
    }
#pragma unroll
    for (int o = 16; o; o >>= 1) s += __shfl_xor_sync(0xffffffffu, s, o);
    if (lane == 0) g_upd[gw] = sigf(s + g_tctrl[gw >> 8]);
}

__global__ __launch_bounds__(256)
void mr_k(const float* __restrict__ Ws)
{
    const int node = blockIdx.x * 8 + (threadIdx.x >> 5);
    const int lane = threadIdx.x & 31;
    if (node >= 16320) return;
    const __nv_bfloat162* hi = (const __nv_bfloat162*)(g_levhi + (size_t)node * 512);
    const __nv_bfloat162* lo = (const __nv_bfloat162*)(g_levlo + (size_t)node * 512);
    const float2* wv = (const float2*)Ws;
    float s = 0.f;
#pragma unroll
    for (int i = 0; i < 8; i++) {
        const int idx = lane + i * 32;
        const __nv_bfloat162 h2 = hi[idx];
        const __nv_bfloat162 l2 = lo[idx];
        const float2 w = wv[idx];
        s = fmaf(__low2float(h2)  + __low2float(l2),  w.x, s);
        s = fmaf(__high2float(h2) + __high2float(l2), w.y, s);
    }
#pragma unroll
    for (int o = 16; o; o >>= 1) s += __shfl_xor_sync(0xffffffffu, s, o);
    if (lane == 0) {
        int l = 1;
#pragma unroll
        for (int t = 2; t <= 8; t++)
            if (node >= c_roff[t]) l = t;
        const int m = 256 >> l;
        const int b = (node - c_roff[l]) / m;
        g_mr[node] = sigf(s + g_sctrl[b]);
    }
}

__global__ void attn_k()
{
    __shared__ float sa[2][256];
    const int b = blockIdx.x, t = threadIdx.x;
    if (t == 0) sa[0][0] = 1.f;
    __syncthreads();
    int cur = 0;
    for (int l = 8; l >= 1; --l) {
        const int m = 256 >> l;
        if (t < m) {
            const float a  = sa[cur][t];
            const float mv = g_mr[c_roff[l] + b * m + t];
            sa[cur ^ 1][2 * t]     = a * (1.f - mv);
            sa[cur ^ 1][2 * t + 1] = a * mv;
        }
        __syncthreads();
        cur ^= 1;
    }
    g_attn[b * 256 + t]       = sa[cur][t];
    g_attn[b * 256 + 128 + t] = sa[cur][128 + t];
}

__global__ __launch_bounds__(512) void treeoutz_k(const float* __restrict__ inputs,
                                                  const float* __restrict__ h0)
{
    __shared__ float sat[256];
    const int b = blockIdx.x, t = threadIdx.x;
    if (t < 256) sat[t] = g_attn[b * 256 + t];
    __syncthreads();
    float a0 = 0.f, a1 = 0.f, a2 = 0.f, a3 = 0.f;
    const float* ip = inputs + (size_t)b * 256 * 512 + t;
#pragma unroll 4
    for (int n = 0; n < 256; n += 4) {
        a0 = fmaf(sat[n],     ip[(size_t)n * 512],       a0);
        a1 = fmaf(sat[n + 1], ip[(size_t)(n + 1) * 512], a1);
        a2 = fmaf(sat[n + 2], ip[(size_t)(n + 2) * 512], a2);
        a3 = fmaf(sat[n + 3], ip[(size_t)(n + 3) * 512], a3);
    }
    const float acc = (a0 + a1) + (a2 + a3);
    const __nv_bfloat16 th = __float2bfloat16(acc);
    g_zAhi[b * 1024 + t] = th;
    g_zAlo[b * 1024 + t] = __float2bfloat16(acc - __bfloat162float(th));
    const float hv = h0[b * 512 + t];
    const __nv_bfloat16 hh = __float2bfloat16(hv);
    g_zAhi[b * 1024 + 512 + t] = hh;
    g_zAlo[b * 1024 + 512 + t] = __float2bfloat16(hv - __bfloat162float(hh));
}

__global__ __launch_bounds__(512) void gate_k(
    const float* __restrict__ c0, const float* __restrict__ bias,
    float* __restrict__ hout, float* __restrict__ cout)
{
    const int b = blockIdx.x, u = threadIdx.x;
    const size_t zo0 = (size_t)b * 2048;
    const float zi = g_z4[zo0 + u]        + g_z4[131072 + zo0 + u]
                   + g_z4[262144 + zo0 + u] + g_z4[393216 + zo0 + u] + bias[u];
    const float zf = g_z4[zo0 + 512 + u]  + g_z4[131072 + zo0 + 512 + u]
                   + g_z4[262144 + zo0 + 512 + u] + g_z4[393216 + zo0 + 512 + u] + bias[512 + u];
    const float zg = g_z4[zo0 + 1024 + u] + g_z4[131072 + zo0 + 1024 + u]
                   + g_z4[262144 + zo0 + 1024 + u] + g_z4[393216 + zo0 + 1024 + u] + bias[1024 + u];
    const float zo = g_z4[zo0 + 1536 + u] + g_z4[131072 + zo0 + 1536 + u]
                   + g_z4[262144 + zo0 + 1536 + u] + g_z4[393216 + zo0 + 1536 + u] + bias[1536 + u];
    const float cn = sigf(zf) * c0[b * 512 + u] + sigf(zi) * tanhf(zg);
    hout[b * 512 + u] = sigf(zo) * tanhf(cn);
    cout[b * 512 + u] = cn;
}

// ---------------------------------------------------------------------------
extern "C" void kernel_launch(void* const* d_in, const int* in_sizes, int n_in,
                              void* d_out, int out_size)
{
    const float* inputs = (const float*)d_in[0];
    const float* h0     = (const float*)d_in[1];
    const float* c0     = (const float*)d_in[2];
    const float* W_t    = (const float*)d_in[3];
    const float* W_j    = (const float*)d_in[4];
    const float* W_s    = (const float*)d_in[5];
    const float* W_h    = (const float*)d_in[6];
    const float* W_T    = (const float*)d_in[7];
    const float* kern   = (const float*)d_in[8];
    const float* rec    = (const float*)d_in[9];
    const float* bias   = (const float*)d_in[10];

    float* out      = (float*)d_out;
    float* h_new    = out;
    float* c_new    = out + BSZ * UD;
    float* leaf_new = out + 2 * BSZ * UD;

    float *p_biasc, *p_attn, *p_upd;
    __nv_bfloat16 *p_Ahi, *p_Alo, *p_leafhi, *p_leaflo, *p_levhi, *p_levlo;
    __nv_bfloat16 *p_Wthi, *p_Wtlo, *p_Wjhi, *p_Wjlo, *p_Whhi, *p_Whlo;
    __nv_bfloat16 *p_Bzhi, *p_Bzlo, *p_zAhi, *p_zAlo;
    cudaGetSymbolAddress((void**)&p_biasc,  g_biasc);
    cudaGetSymbolAddress((void**)&p_attn,   g_attn);
    cudaGetSymbolAddress((void**)&p_upd,    g_upd);
    cudaGetSymbolAddress((void**)&p_Ahi,    g_Ahi);
    cudaGetSymbolAddress((void**)&p_Alo,    g_Alo);
    cudaGetSymbolAddress((void**)&p_leafhi, g_leafhi);
    cudaGetSymbolAddress((void**)&p_leaflo, g_leaflo);
    cudaGetSymbolAddress((void**)&p_levhi,  g_levhi);
    cudaGetSymbolAddress((void**)&p_levlo,  g_levlo);
    cudaGetSymbolAddress((void**)&p_Wthi,   g_Wthi);
    cudaGetSymbolAddress((void**)&p_Wtlo,   g_Wtlo);
    cudaGetSymbolAddress((void**)&p_Wjhi,   g_Wjhi);
    cudaGetSymbolAddress((void**)&p_Wjlo,   g_Wjlo);
    cudaGetSymbolAddress((void**)&p_Whhi,   g_Whhi);
    cudaGetSymbolAddress((void**)&p_Whlo,   g_Whlo);
    cudaGetSymbolAddress((void**)&p_Bzhi,   g_Bzhi);
    cudaGetSymbolAddress((void**)&p_Bzlo,   g_Bzlo);
    cudaGetSymbolAddress((void**)&p_zAhi,   g_zAhi);
    cudaGetSymbolAddress((void**)&p_zAlo,   g_zAlo);

    cudaFuncSetAttribute((const void*)tgemm_k<0, 128, 3, 256>,
                         cudaFuncAttributeMaxDynamicSharedMemorySize, SMEM_128);
    cudaFuncSetAttribute((const void*)tgemm_k<1, 128, 3, 256>,
                         cudaFuncAttributeMaxDynamicSharedMemorySize, SMEM_128);
    cudaFuncSetAttribute((const void*)joinp_k,
                         cudaFuncAttributeMaxDynamicSharedMemorySize, SMEM_64);
    cudaFuncSetAttribute((const void*)lstmgemm_k,
                         cudaFuncAttributeMaxDynamicSharedMemorySize, SMEM_64);

    // streams/events created once (first call is the un-captured correctness run)
    static cudaStream_t s1 = nullptr;
    static cudaEvent_t evFork, evPrepB, evLeaf, evUpd, evAttn, evGate;
    if (!s1) {
        cudaStreamCreateWithFlags(&s1, cudaStreamNonBlocking);
        cudaEventCreateWithFlags(&evFork,  cudaEventDisableTiming);
        cudaEventCreateWithFlags(&evPrepB, cudaEventDisableTiming);
        cudaEventCreateWithFlags(&evLeaf,  cudaEventDisableTiming);
        cudaEventCreateWithFlags(&evUpd,   cudaEventDisableTiming);
        cudaEventCreateWithFlags(&evAttn,  cudaEventDisableTiming);
        cudaEventCreateWithFlags(&evGate,  cudaEventDisableTiming);
    }

    // ---- proper fork: s1's first captured op must be a wait on the origin ----
    cudaEventRecord(evFork, 0);
    cudaStreamWaitEvent(s1, evFork, 0);

    // main: prep_a (input + Wt)  |  s1: prep_b (Wh/Wj/kern/rec/ctrl/biasc)
    prepa_k<<<8448, 256>>>((const float4*)inputs, W_t);
    prepb_k<<<2944, 256, 0, s1>>>(h0, W_j, W_s, W_h, W_T, kern, rec);
    cudaEventRecord(evPrepB, s1);

    // main: leaf embed
    tgemm_k<0, 128, 3, 256><<<dim3(128, 4), 256, SMEM_128>>>(
        p_Ahi, p_Alo, p_Wthi, p_Wtlo, nullptr, p_leafhi, p_leaflo,
        16384, 512, 512, 512, 512, nullptr, nullptr, nullptr);
    cudaEventRecord(evLeaf, 0);

    // s1: upd (needs leaf + tctrl) — overlaps join chain
    cudaStreamWaitEvent(s1, evLeaf, 0);
    upd_k<<<2048, 256, 0, s1>>>(W_T);
    cudaEventRecord(evUpd, s1);

    // main: join chain (needs Wj from prep_b)
    cudaStreamWaitEvent(0, evPrepB, 0);
    tgemm_k<0, 128, 3, 256><<<dim3(64, 4), 256, SMEM_128>>>(
        p_leafhi, p_leaflo, p_Wjhi, p_Wjlo, nullptr,
        p_levhi + (size_t)h_roff[1] * 512, p_levlo + (size_t)h_roff[1] * 512,
        8192, 1024, 1024, 1024, 512, nullptr, nullptr, nullptr);
    tgemm_k<0, 128, 3, 256><<<dim3(32, 4), 256, SMEM_128>>>(
        p_levhi + (size_t)h_roff[1] * 512, p_levlo + (size_t)h_roff[1] * 512,
        p_Wjhi, p_Wjlo, nullptr,
        p_levhi + (size_t)h_roff[2] * 512, p_levlo + (size_t)h_roff[2] * 512,
        4096, 1024, 1024, 1024, 512, nullptr, nullptr, nullptr);
    joinp_k<<<148, 256, SMEM_64>>>(p_levhi, p_levlo, p_Wjhi, p_Wjlo);

    // main: mr + attention
    mr_k<<<2040, 256>>>(W_s);
    attn_k<<<64, 128>>>();
    cudaEventRecord(evAttn, 0);

    // s1: LSTM chain (needs attn) — overlaps cand GEMM
    cudaStreamWaitEvent(s1, evAttn, 0);
    treeoutz_k<<<64, 512, 0, s1>>>(inputs, h0);
    lstmgemm_k<<<dim3(4, 32), 256, SMEM_64, s1>>>(p_zAhi, p_zAlo, p_Bzhi, p_Bzlo);
    gate_k<<<64, 512, 0, s1>>>(c0, bias, h_new, c_new);
    cudaEventRecord(evGate, s1);

    // main: cand GEMM (needs upd)
    cudaStreamWaitEvent(0, evUpd, 0);
    tgemm_k<1, 128, 3, 256><<<dim3(128, 4), 256, SMEM_128>>>(
        p_leafhi, p_leaflo, p_Whhi, p_Whlo, leaf_new, p_leafhi, p_leaflo,
        16384, 512, 512, 512, 512, p_biasc, p_attn, p_upd);

    // join s1 back into main before capture ends
    cudaStreamWaitEvent(0, evGate, 0);
}